// round 11
// baseline (speedup 1.0000x reference)
#include <cuda_runtime.h>
#include <cuda_fp16.h>
#include <cstdint>

// ---------------------------------------------------------------------------
// Problem constants
// ---------------------------------------------------------------------------
#define BB   2
#define LL   2048
#define DM   512
#define HH   8
#define KT   5
#define HW   64
#define MTOT (BB*LL)                  // 4096
#define NKV_ (HH*KT*HW)               // 2560
#define NQK  (DM + NKV_)              // 3072  (q then k)
#define NTOT (NQK + NKV_)             // 5632
#define KBASE (DM)                    // k starts at col 512 in PQK
#define KD   512

// ---------------------------------------------------------------------------
// Device scratch
// ---------------------------------------------------------------------------
__device__ __half g_Xh  [(size_t)MTOT * KD];      //  4.2 MB
__device__ __half g_Wh  [(size_t)NTOT * KD];      //  5.8 MB [qw;kw;vw]
__device__ __half g_OWh [(size_t)DM * KD];        //  0.5 MB
__device__ float  g_PQK [(size_t)MTOT * NQK];     // 50.3 MB fp32 q,k projections
__device__ __half g_PV  [(size_t)MTOT * NKV_];    // 21.0 MB fp16 v projections
__device__ __half g_ATTN[(size_t)MTOT * DM];      //  4.2 MB

// ---------------------------------------------------------------------------
// Helpers
// ---------------------------------------------------------------------------
__device__ __forceinline__ void ldm_x4(uint32_t& r0, uint32_t& r1, uint32_t& r2, uint32_t& r3,
                                       const void* p) {
    uint32_t a = (uint32_t)__cvta_generic_to_shared(p);
    asm volatile("ldmatrix.sync.aligned.m8n8.x4.shared.b16 {%0,%1,%2,%3}, [%4];"
                 : "=r"(r0), "=r"(r1), "=r"(r2), "=r"(r3) : "r"(a));
}

__device__ __forceinline__ void mma_fp16(float d[4], const uint32_t a[4], const uint32_t b[2]) {
    asm volatile(
        "mma.sync.aligned.m16n8k16.row.col.f32.f16.f16.f32 "
        "{%0,%1,%2,%3}, {%4,%5,%6,%7}, {%8,%9}, {%0,%1,%2,%3};\n"
        : "+f"(d[0]), "+f"(d[1]), "+f"(d[2]), "+f"(d[3])
        : "r"(a[0]), "r"(a[1]), "r"(a[2]), "r"(a[3]), "r"(b[0]), "r"(b[1]));
}

#define CP_ASYNC16(smem_ptr, gptr) \
    asm volatile("cp.async.cg.shared.global [%0], [%1], 16;\n" \
                 :: "r"((uint32_t)__cvta_generic_to_shared(smem_ptr)), "l"(gptr))

// ---------------------------------------------------------------------------
// K0: convert inputs to fp16
// ---------------------------------------------------------------------------
#define NX_  (MTOT*KD)
#define NQW_ (DM*KD)
#define NKW_ (NKV_*KD)
#define NW_  (NQW_ + 2*NKW_)
#define PREP_TOT (NX_ + NW_ + NQW_)

__global__ void prep_kernel(const float* __restrict__ x,
                            const float* __restrict__ qw,
                            const float* __restrict__ kw,
                            const float* __restrict__ vw,
                            const float* __restrict__ ow) {
    int i = blockIdx.x * blockDim.x + threadIdx.x;
    if (i >= PREP_TOT) return;
    if (i < NX_) {
        g_Xh[i] = __float2half_rn(x[i]);
    } else {
        int j = i - NX_;
        if (j < NW_) {
            float v;
            if (j < NQW_)             v = qw[j];
            else if (j < NQW_ + NKW_) v = kw[j - NQW_];
            else                      v = vw[j - NQW_ - NKW_];
            g_Wh[j] = __float2half_rn(v);
        } else {
            g_OWh[j - NW_] = __float2half_rn(ow[j - NW_]);
        }
    }
}

#define BKH 32
#define SKH 40
#define NSTG 3

// ---------------------------------------------------------------------------
// K1: big-tile fp16 GEMM. CTA 128x256, 8 warps (2x4), warp tile 64x64,
// BK=32, 3-stage cp.async, single __syncthreads per K-iter.
// Mixed output: n0 < NQK -> fp32 PQK, else fp16 PV (split 3072 % 256 == 0).
// Per k-chunk: 8 ldmatrix.x4 feed 32 MMAs (4 MMA / LDSM).
// ---------------------------------------------------------------------------
#define BM1 128
#define BN1 256

__global__ __launch_bounds__(256, 1) void gemm_big(
    const __half* __restrict__ A, const __half* __restrict__ B,
    float* __restrict__ C32, __half* __restrict__ C16)
{
    extern __shared__ __half sh[];
    const int STG = (BM1 + BN1) * SKH;       // 15360 halfs per stage

    const int n0  = blockIdx.x * BN1;
    const int m0  = blockIdx.y * BM1;
    const int tid = threadIdx.x;
    const int warp = tid >> 5, lane = tid & 31;
    const int wm = (warp >> 2) * 64;         // 0, 64
    const int wn = (warp & 3) * 64;          // 0, 64, 128, 192
    const int g  = lane >> 2, t = lane & 3;

    float acc[4][8][4];
    #pragma unroll
    for (int mt = 0; mt < 4; mt++)
        #pragma unroll
        for (int nt = 0; nt < 8; nt++)
            #pragma unroll
            for (int i = 0; i < 4; i++) acc[mt][nt][i] = 0.f;

    const __half* Ab = A + (size_t)m0 * KD;
    const __half* Bb = B + (size_t)n0 * KD;

    // Stage load: rows of 64 B = 4 x 16 B chunks. A: 512 chunks, B: 1024.
    auto load_stage = [&](int s, int k0) {
        __half* as = sh + (s % NSTG) * STG;
        __half* bs = as + BM1 * SKH;
        #pragma unroll
        for (int i = 0; i < 2; ++i) {
            int idx = tid + 256 * i;
            int r = idx >> 2, c = (idx & 3) * 8;
            CP_ASYNC16(&as[r * SKH + c], Ab + (size_t)r * KD + k0 + c);
        }
        #pragma unroll
        for (int i = 0; i < 4; ++i) {
            int idx = tid + 256 * i;
            int r = idx >> 2, c = (idx & 3) * 8;
            CP_ASYNC16(&bs[r * SKH + c], Bb + (size_t)r * KD + k0 + c);
        }
        asm volatile("cp.async.commit_group;\n" ::);
    };

    const int NKt = KD / BKH;   // 16
    load_stage(0, 0);
    load_stage(1, BKH);

    const int rowA  = lane & 15;
    const int kselA = ((lane >> 4) & 1) * 8;
    const int rowB  = lane & 7;
    const int nselB = ((lane >> 4) & 1) * 8;
    const int kselB = ((lane >> 3) & 1) * 8;

    for (int kt = 0; kt < NKt; ++kt) {
        if (kt + 1 < NKt) asm volatile("cp.async.wait_group 1;\n" ::);
        else              asm volatile("cp.async.wait_group 0;\n" ::);
        __syncthreads();                       // single barrier per iter

        if (kt + 2 < NKt) load_stage(kt + 2, (kt + 2) * BKH);

        const __half* as = sh + (kt % NSTG) * STG;
        const __half* bs = as + BM1 * SKH;

        #pragma unroll
        for (int ch = 0; ch < 2; ++ch) {
            const int kb = ch * 16;
            uint32_t af[4][4], bf[8][2];
            #pragma unroll
            for (int mt = 0; mt < 4; mt++)
                ldm_x4(af[mt][0], af[mt][1], af[mt][2], af[mt][3],
                       &as[(wm + mt * 16 + rowA) * SKH + kb + kselA]);
            #pragma unroll
            for (int p = 0; p < 4; p++)
                ldm_x4(bf[2*p][0], bf[2*p][1], bf[2*p+1][0], bf[2*p+1][1],
                       &bs[(wn + p * 16 + nselB + rowB) * SKH + kb + kselB]);
            #pragma unroll
            for (int mt = 0; mt < 4; mt++)
                #pragma unroll
                for (int nt = 0; nt < 8; nt++)
                    mma_fp16(acc[mt][nt], af[mt], bf[nt]);
        }
    }

    // Epilogue: c0:(g,2t) c1:(g,2t+1) c2:(g+8,2t) c3:(g+8,2t+1)
    const bool f32out = (n0 < NQK);
    #pragma unroll
    for (int mt = 0; mt < 4; mt++) {
        int r = m0 + wm + mt * 16 + g;
        #pragma unroll
        for (int nt = 0; nt < 8; nt++) {
            int c = n0 + wn + nt * 8 + 2 * t;
            if (f32out) {
                *(float2*)&C32[(size_t)(r    ) * NQK + c] =
                    make_float2(acc[mt][nt][0], acc[mt][nt][1]);
                *(float2*)&C32[(size_t)(r + 8) * NQK + c] =
                    make_float2(acc[mt][nt][2], acc[mt][nt][3]);
            } else {
                int c16 = c - NQK;
                *(__half2*)&C16[(size_t)(r    ) * NKV_ + c16] =
                    __floats2half2_rn(acc[mt][nt][0], acc[mt][nt][1]);
                *(__half2*)&C16[(size_t)(r + 8) * NKV_ + c16] =
                    __floats2half2_rn(acc[mt][nt][2], acc[mt][nt][3]);
            }
        }
    }
}

// ---------------------------------------------------------------------------
// K3: small fp16 GEMM (proven round-10 shape). CTA 64x128, 8 warps,
// warp tile 32x32, BK=32, 3-stage, single sync. fp32 out + bias.
// ---------------------------------------------------------------------------
#define BM3 64
#define BN3 128

__global__ __launch_bounds__(256, 2) void gemm_small(
    const __half* __restrict__ A, const __half* __restrict__ B,
    float* __restrict__ C, int ldc, const float* __restrict__ bias)
{
    extern __shared__ __half sh[];
    const int STG = (BM3 + BN3) * SKH;

    const int n0  = blockIdx.x * BN3;
    const int m0  = blockIdx.y * BM3;
    const int tid = threadIdx.x;
    const int warp = tid >> 5, lane = tid & 31;
    const int wm = (warp >> 2) * 32;
    const int wn = (warp & 3) * 32;
    const int g  = lane >> 2, t = lane & 3;

    float acc[2][4][4];
    #pragma unroll
    for (int mt = 0; mt < 2; mt++)
        #pragma unroll
        for (int nt = 0; nt < 4; nt++)
            #pragma unroll
            for (int i = 0; i < 4; i++) acc[mt][nt][i] = 0.f;

    const __half* Ab = A + (size_t)m0 * KD;
    const __half* Bb = B + (size_t)n0 * KD;

    auto load_stage = [&](int s, int k0) {
        __half* as = sh + (s % NSTG) * STG;
        __half* bs = as + BM3 * SKH;
        {   // A: 256 chunks
            int r = tid >> 2, c = (tid & 3) * 8;
            CP_ASYNC16(&as[r * SKH + c], Ab + (size_t)r * KD + k0 + c);
        }
        #pragma unroll
        for (int i = 0; i < 2; ++i) {        // B: 512 chunks
            int idx = tid + 256 * i;
            int r = idx >> 2, c = (idx & 3) * 8;
            CP_ASYNC16(&bs[r * SKH + c], Bb + (size_t)r * KD + k0 + c);
        }
        asm volatile("cp.async.commit_group;\n" ::);
    };

    const int NKt = KD / BKH;
    load_stage(0, 0);
    load_stage(1, BKH);

    const int rowA  = lane & 15;
    const int kselA = ((lane >> 4) & 1) * 8;
    const int rowB  = lane & 7;
    const int nselB = ((lane >> 4) & 1) * 8;
    const int kselB = ((lane >> 3) & 1) * 8;

    for (int kt = 0; kt < NKt; ++kt) {
        if (kt + 1 < NKt) asm volatile("cp.async.wait_group 1;\n" ::);
        else              asm volatile("cp.async.wait_group 0;\n" ::);
        __syncthreads();

        if (kt + 2 < NKt) load_stage(kt + 2, (kt + 2) * BKH);

        const __half* as = sh + (kt % NSTG) * STG;
        const __half* bs = as + BM3 * SKH;

        #pragma unroll
        for (int ch = 0; ch < 2; ++ch) {
            const int kb = ch * 16;
            uint32_t af[2][4], bf[4][2];
            #pragma unroll
            for (int mt = 0; mt < 2; mt++)
                ldm_x4(af[mt][0], af[mt][1], af[mt][2], af[mt][3],
                       &as[(wm + mt * 16 + rowA) * SKH + kb + kselA]);
            #pragma unroll
            for (int p = 0; p < 2; p++)
                ldm_x4(bf[2*p][0], bf[2*p][1], bf[2*p+1][0], bf[2*p+1][1],
                       &bs[(wn + p * 16 + nselB + rowB) * SKH + kb + kselB]);
            #pragma unroll
            for (int mt = 0; mt < 2; mt++)
                #pragma unroll
                for (int nt = 0; nt < 4; nt++)
                    mma_fp16(acc[mt][nt], af[mt], bf[nt]);
        }
    }

    #pragma unroll
    for (int mt = 0; mt < 2; mt++) {
        int r = m0 + wm + mt * 16 + g;
        #pragma unroll
        for (int nt = 0; nt < 4; nt++) {
            int c = n0 + wn + nt * 8 + 2 * t;
            float b0 = bias[c], b1 = bias[c + 1];
            *(float2*)&C[(size_t)(r    ) * ldc + c] =
                make_float2(acc[mt][nt][0] + b0, acc[mt][nt][1] + b1);
            *(float2*)&C[(size_t)(r + 8) * ldc + c] =
                make_float2(acc[mt][nt][2] + b0, acc[mt][nt][3] + b1);
        }
    }
}

// ---------------------------------------------------------------------------
// K2: attention. One warp per (b,l,h). q,k fp32 from PQK; v fp16 from PV.
// Softmax over 5 taps, weighted V sum, /sqrt(64) -> fp16 ATTN.
// ---------------------------------------------------------------------------
__global__ __launch_bounds__(256) void attn_kernel(const float* __restrict__ qb,
                                                   const float* __restrict__ kb,
                                                   const float* __restrict__ vb) {
    int w    = (blockIdx.x * blockDim.x + threadIdx.x) >> 5;
    int lane = threadIdx.x & 31;
    if (w >= MTOT * HH) return;

    int h   = w & 7;
    int row = w >> 3;
    int l   = row & (LL - 1);
    int b   = row >> 11;
    int d   = 1 << (h & 3);

    const float2*  QK2 = (const float2*)g_PQK;
    const __half2* V2  = (const __half2*)g_PV;
    const int NQK2 = NQK / 2;
    const int NV2  = NKV_ / 2;
    int qoff = h * HW;
    int e0 = qoff + 2 * lane;

    float2 q = QK2[(size_t)row * NQK2 + (qoff >> 1) + lane];
    q.x += qb[e0]; q.y += qb[e0 + 1];

    float lg[KT];
    float2 vv[KT];
    #pragma unroll
    for (int kk = 0; kk < KT; ++kk) {
        int sl   = l + (kk - 2) * d;
        int kidx = (h * KT + kk) * HW;
        int be   = kidx + 2 * lane;
        float2 kf, vf;
        if (sl >= 0 && sl < LL) {
            int srow = b * LL + sl;
            kf = QK2[(size_t)srow * NQK2 + ((KBASE + kidx) >> 1) + lane];
            vf = __half22float2(V2[(size_t)srow * NV2 + (kidx >> 1) + lane]);
            kf.x += kb[be]; kf.y += kb[be + 1];
            vf.x += vb[be]; vf.y += vb[be + 1];
        } else {
            kf = make_float2(kb[be], kb[be + 1]);
            vf = make_float2(vb[be], vb[be + 1]);
        }
        vv[kk] = vf;
        float p = q.x * kf.x + q.y * kf.y;
        #pragma unroll
        for (int s = 16; s > 0; s >>= 1) p += __shfl_xor_sync(0xffffffffu, p, s);
        lg[kk] = p;
    }

    float mx = lg[0];
    #pragma unroll
    for (int kk = 1; kk < KT; ++kk) mx = fmaxf(mx, lg[kk]);
    float e[KT], se = 0.f;
    #pragma unroll
    for (int kk = 0; kk < KT; ++kk) { e[kk] = __expf(lg[kk] - mx); se += e[kk]; }
    float inv = 0.125f / se;

    float a0 = 0.f, a1 = 0.f;
    #pragma unroll
    for (int kk = 0; kk < KT; ++kk) { a0 += e[kk] * vv[kk].x; a1 += e[kk] * vv[kk].y; }
    a0 *= inv; a1 *= inv;

    __half2* O2 = (__half2*)g_ATTN;
    O2[((size_t)row * DM + qoff) / 2 + lane] = __floats2half2_rn(a0, a1);
}

// ---------------------------------------------------------------------------
// Launch
// ---------------------------------------------------------------------------
extern "C" void kernel_launch(void* const* d_in, const int* in_sizes, int n_in,
                              void* d_out, int out_size) {
    const float* x   = (const float*)d_in[0];
    const float* q_w = (const float*)d_in[1];
    const float* q_b = (const float*)d_in[2];
    const float* k_w = (const float*)d_in[3];
    const float* k_b = (const float*)d_in[4];
    const float* v_w = (const float*)d_in[5];
    const float* v_b = (const float*)d_in[6];
    const float* o_w = (const float*)d_in[7];
    const float* o_b = (const float*)d_in[8];

    __half *Xh, *Wh, *OWh, *PV, *ATTN;
    float *PQK;
    cudaGetSymbolAddress((void**)&Xh,   g_Xh);
    cudaGetSymbolAddress((void**)&Wh,   g_Wh);
    cudaGetSymbolAddress((void**)&OWh,  g_OWh);
    cudaGetSymbolAddress((void**)&PQK,  g_PQK);
    cudaGetSymbolAddress((void**)&PV,   g_PV);
    cudaGetSymbolAddress((void**)&ATTN, g_ATTN);

    const int smem1 = NSTG * (BM1 + BN1) * SKH * 2;  // 92160 B
    const int smem3 = NSTG * (BM3 + BN3) * SKH * 2;  // 46080 B
    cudaFuncSetAttribute(gemm_big,
                         cudaFuncAttributeMaxDynamicSharedMemorySize, smem1);
    cudaFuncSetAttribute(gemm_small,
                         cudaFuncAttributeMaxDynamicSharedMemorySize, smem3);

    // K0: convert to fp16
    prep_kernel<<<(PREP_TOT + 255) / 256, 256>>>(x, q_w, k_w, v_w, o_w);

    // K1: cols 0..3071 -> PQK fp32, cols 3072..5631 -> PV fp16
    gemm_big<<<dim3(NTOT / BN1, MTOT / BM1), 256, smem1>>>(Xh, Wh, PQK, PV);

    // K2: attention -> ATTN[4096, 512] fp16
    attn_kernel<<<(MTOT * HH * 32) / 256, 256>>>(q_b, k_b, v_b);

    // K3: OUT = ATTN @ OWh^T + o_b
    gemm_small<<<dim3(DM / BN3, MTOT / BM3), 256, smem3>>>(
        ATTN, OWh, (float*)d_out, DM, o_b);
}

// round 12
// speedup vs baseline: 1.2036x; 1.2036x over previous
#include <cuda_runtime.h>
#include <cuda_fp16.h>
#include <cstdint>

// ---------------------------------------------------------------------------
// Problem constants
// ---------------------------------------------------------------------------
#define BB   2
#define LL   2048
#define DM   512
#define HH   8
#define KT   5
#define HW   64
#define MTOT (BB*LL)                  // 4096
#define NKV_ (HH*KT*HW)               // 2560
#define NQK  (DM + NKV_)              // 3072  (q then k)
#define NTOT (NQK + NKV_)             // 5632
#define KBASE (DM)                    // k starts at col 512 in PQK
#define KD   512

// ---------------------------------------------------------------------------
// Device scratch
// ---------------------------------------------------------------------------
__device__ __half g_Xh  [(size_t)MTOT * KD];      //  4.2 MB
__device__ __half g_Wh  [(size_t)NTOT * KD];      //  5.8 MB [qw;kw;vw]
__device__ __half g_OWh [(size_t)DM * KD];        //  0.5 MB
__device__ float  g_PQK [(size_t)MTOT * NQK];     // 50.3 MB fp32 q,k projections
__device__ __half g_PV  [(size_t)MTOT * NKV_];    // 21.0 MB fp16 v projections
__device__ __half g_ATTN[(size_t)MTOT * DM];      //  4.2 MB

// ---------------------------------------------------------------------------
// Helpers
// ---------------------------------------------------------------------------
__device__ __forceinline__ void ldm_x4(uint32_t& r0, uint32_t& r1, uint32_t& r2, uint32_t& r3,
                                       const void* p) {
    uint32_t a = (uint32_t)__cvta_generic_to_shared(p);
    asm volatile("ldmatrix.sync.aligned.m8n8.x4.shared.b16 {%0,%1,%2,%3}, [%4];"
                 : "=r"(r0), "=r"(r1), "=r"(r2), "=r"(r3) : "r"(a));
}

__device__ __forceinline__ void mma_fp16(float d[4], const uint32_t a[4], const uint32_t b[2]) {
    asm volatile(
        "mma.sync.aligned.m16n8k16.row.col.f32.f16.f16.f32 "
        "{%0,%1,%2,%3}, {%4,%5,%6,%7}, {%8,%9}, {%0,%1,%2,%3};\n"
        : "+f"(d[0]), "+f"(d[1]), "+f"(d[2]), "+f"(d[3])
        : "r"(a[0]), "r"(a[1]), "r"(a[2]), "r"(a[3]), "r"(b[0]), "r"(b[1]));
}

#define CP_ASYNC16(smem_ptr, gptr) \
    asm volatile("cp.async.cg.shared.global [%0], [%1], 16;\n" \
                 :: "r"((uint32_t)__cvta_generic_to_shared(smem_ptr)), "l"(gptr))

// ---------------------------------------------------------------------------
// K0: convert inputs to fp16, float4-vectorized (4 elems / thread)
// ---------------------------------------------------------------------------
#define NX_  (MTOT*KD)
#define NQW_ (DM*KD)
#define NKW_ (NKV_*KD)
#define NW_  (NQW_ + 2*NKW_)
#define NX4  (NX_/4)
#define NQW4 (NQW_/4)
#define NKW4 (NKW_/4)
#define NW4  (NW_/4)
#define PREP4 (NX4 + NW4 + NQW4)     // 1310720

__device__ __forceinline__ void cvt4(__half* dst, float4 f) {
    __half2* d2 = (__half2*)dst;
    d2[0] = __floats2half2_rn(f.x, f.y);
    d2[1] = __floats2half2_rn(f.z, f.w);
}

__global__ void prep_kernel(const float* __restrict__ x,
                            const float* __restrict__ qw,
                            const float* __restrict__ kw,
                            const float* __restrict__ vw,
                            const float* __restrict__ ow) {
    int i = blockIdx.x * blockDim.x + threadIdx.x;
    if (i >= PREP4) return;
    if (i < NX4) {
        cvt4(g_Xh + 4 * (size_t)i, ((const float4*)x)[i]);
    } else {
        int j = i - NX4;
        if (j < NW4) {
            float4 f;
            if (j < NQW4)            f = ((const float4*)qw)[j];
            else if (j < NQW4+NKW4)  f = ((const float4*)kw)[j - NQW4];
            else                     f = ((const float4*)vw)[j - NQW4 - NKW4];
            cvt4(g_Wh + 4 * (size_t)j, f);
        } else {
            int p = j - NW4;
            cvt4(g_OWh + 4 * (size_t)p, ((const float4*)ow)[p]);
        }
    }
}

// ---------------------------------------------------------------------------
// fp16 GEMM (round-10 winner): blocks with n0 < NSPLIT write fp32 to C32,
// others fp16 to C16. CTA BMt x 128, 8 warps (2x4), warp tile (BMt/2) x 32,
// BK=32, 3-stage cp.async, ONE __syncthreads per K-iteration.
// smem stride 40 fp16 (80 B): conflict-free ldmatrix.
// ---------------------------------------------------------------------------
#define BN  128
#define BKH 32
#define SKH 40
#define NSTG 3

template <int BMt, int NSPLIT, bool HAS_BIAS>
__global__ __launch_bounds__(256, 2) void gemm_fp16(
    const __half* __restrict__ A, const __half* __restrict__ B,
    float* __restrict__ C32, int ldc32,
    __half* __restrict__ C16, int ldc16,
    const float* __restrict__ bias)
{
    extern __shared__ __half sh[];
    const int STG = (BMt + BN) * SKH;
    constexpr int MT = BMt / 32;

    const int n0  = blockIdx.x * BN;
    const int m0  = blockIdx.y * BMt;
    const int tid = threadIdx.x;
    const int warp = tid >> 5, lane = tid & 31;
    const int wm = (warp >> 2) * (16 * MT);
    const int wn = (warp & 3) * 32;
    const int g  = lane >> 2, t = lane & 3;

    float acc[MT][4][4];
    #pragma unroll
    for (int mt = 0; mt < MT; mt++)
        #pragma unroll
        for (int nt = 0; nt < 4; nt++)
            #pragma unroll
            for (int i = 0; i < 4; i++) acc[mt][nt][i] = 0.f;

    const __half* Ab = A + (size_t)m0 * KD;
    const __half* Bb = B + (size_t)n0 * KD;

    auto load_stage = [&](int s, int k0) {
        __half* as = sh + (s % NSTG) * STG;
        __half* bs = as + BMt * SKH;
        #pragma unroll
        for (int i = 0; i < BMt / 64; ++i) {
            int idx = tid + 256 * i;
            int r = idx >> 2, c = (idx & 3) * 8;
            CP_ASYNC16(&as[r * SKH + c], Ab + (size_t)r * KD + k0 + c);
        }
        #pragma unroll
        for (int i = 0; i < 2; ++i) {
            int idx = tid + 256 * i;
            int r = idx >> 2, c = (idx & 3) * 8;
            CP_ASYNC16(&bs[r * SKH + c], Bb + (size_t)r * KD + k0 + c);
        }
        asm volatile("cp.async.commit_group;\n" ::);
    };

    const int NKt = KD / BKH;   // 16
    load_stage(0, 0);
    load_stage(1, BKH);

    const int rowA  = lane & 15;
    const int kselA = ((lane >> 4) & 1) * 8;
    const int rowB  = lane & 7;
    const int nselB = ((lane >> 4) & 1) * 8;
    const int kselB = ((lane >> 3) & 1) * 8;

    for (int kt = 0; kt < NKt; ++kt) {
        if (kt + 1 < NKt) asm volatile("cp.async.wait_group 1;\n" ::);
        else              asm volatile("cp.async.wait_group 0;\n" ::);
        __syncthreads();

        if (kt + 2 < NKt) load_stage(kt + 2, (kt + 2) * BKH);

        const __half* as = sh + (kt % NSTG) * STG;
        const __half* bs = as + BMt * SKH;

        #pragma unroll
        for (int ch = 0; ch < 2; ++ch) {
            const int kb = ch * 16;
            uint32_t af[MT][4], bf[4][2];
            #pragma unroll
            for (int mt = 0; mt < MT; mt++)
                ldm_x4(af[mt][0], af[mt][1], af[mt][2], af[mt][3],
                       &as[(wm + mt * 16 + rowA) * SKH + kb + kselA]);
            #pragma unroll
            for (int p = 0; p < 2; p++)
                ldm_x4(bf[2*p][0], bf[2*p][1], bf[2*p+1][0], bf[2*p+1][1],
                       &bs[(wn + p * 16 + nselB + rowB) * SKH + kb + kselB]);
            #pragma unroll
            for (int mt = 0; mt < MT; mt++)
                #pragma unroll
                for (int nt = 0; nt < 4; nt++)
                    mma_fp16(acc[mt][nt], af[mt], bf[nt]);
        }
    }

    const bool f32out = (n0 < NSPLIT);
    #pragma unroll
    for (int mt = 0; mt < MT; mt++) {
        int r = m0 + wm + mt * 16 + g;
        #pragma unroll
        for (int nt = 0; nt < 4; nt++) {
            int c = n0 + wn + nt * 8 + 2 * t;
            float o0 = acc[mt][nt][0], o1 = acc[mt][nt][1];
            float o2 = acc[mt][nt][2], o3 = acc[mt][nt][3];
            if (HAS_BIAS) {
                float b0 = bias[c], b1 = bias[c + 1];
                o0 += b0; o1 += b1; o2 += b0; o3 += b1;
            }
            if (f32out) {
                *(float2*)&C32[(size_t)(r    ) * ldc32 + c] = make_float2(o0, o1);
                *(float2*)&C32[(size_t)(r + 8) * ldc32 + c] = make_float2(o2, o3);
            } else {
                int c16 = c - NSPLIT;
                *(__half2*)&C16[(size_t)(r    ) * ldc16 + c16] = __floats2half2_rn(o0, o1);
                *(__half2*)&C16[(size_t)(r + 8) * ldc16 + c16] = __floats2half2_rn(o2, o3);
            }
        }
    }
}

// ---------------------------------------------------------------------------
// K2: attention, restructured for latency.
// Warp = (row, head-pair). Lanes 0-15: head 2hp, lanes 16-31: head 2hp+1.
// Each lane covers 4 elems (float4 / 8B loads). All 5 tap partial dots are
// computed first (loads in flight together), then 5 independent 4-level
// shfl trees (width 16) pipeline. Softmax + V mix per lane, vectorized store.
// ---------------------------------------------------------------------------
__global__ __launch_bounds__(256) void attn_kernel(const float* __restrict__ qb,
                                                   const float* __restrict__ kb,
                                                   const float* __restrict__ vb) {
    int w    = (blockIdx.x * blockDim.x + threadIdx.x) >> 5;
    int lane = threadIdx.x & 31;
    if (w >= MTOT * (HH / 2)) return;

    int hp  = w & 3;
    int row = w >> 2;
    int l   = row & (LL - 1);
    int b   = row >> 11;
    int h   = hp * 2 + (lane >> 4);
    int li  = lane & 15;
    int d   = 1 << (h & 3);

    const float4* QK4 = (const float4*)g_PQK;
    const int NQK4 = NQK / 4;            // 768
    int qoff = h * HW;
    int e0   = li * 4;                   // element within 64-wide head

    float4 q = QK4[(size_t)row * NQK4 + ((qoff + e0) >> 2)];
    {
        float4 qb4 = ((const float4*)qb)[(qoff + e0) >> 2];
        q.x += qb4.x; q.y += qb4.y; q.z += qb4.z; q.w += qb4.w;
    }

    float  p[KT];
    float4 vv[KT];
    #pragma unroll
    for (int kk = 0; kk < KT; ++kk) {
        int sl   = l + (kk - 2) * d;
        int kidx = (h * KT + kk) * HW + e0;
        float4 kb4 = ((const float4*)kb)[kidx >> 2];
        float4 vb4 = ((const float4*)vb)[kidx >> 2];
        float4 kf, vf;
        if (sl >= 0 && sl < LL) {
            int srow = b * LL + sl;
            kf = QK4[(size_t)srow * NQK4 + ((KBASE + kidx) >> 2)];
            uint2 vraw = *(const uint2*)(g_PV + (size_t)srow * NKV_ + kidx);
            __half2 v01 = *(__half2*)&vraw.x, v23 = *(__half2*)&vraw.y;
            float2 f01 = __half22float2(v01), f23 = __half22float2(v23);
            kf.x += kb4.x; kf.y += kb4.y; kf.z += kb4.z; kf.w += kb4.w;
            vf = make_float4(f01.x + vb4.x, f01.y + vb4.y,
                             f23.x + vb4.z, f23.y + vb4.w);
        } else {
            kf = kb4;
            vf = vb4;
        }
        vv[kk] = vf;
        p[kk] = q.x * kf.x + q.y * kf.y + q.z * kf.z + q.w * kf.w;
    }

    // 5 independent reductions over the 16-lane group (xor 8,4,2,1)
    #pragma unroll
    for (int s = 8; s > 0; s >>= 1)
        #pragma unroll
        for (int kk = 0; kk < KT; ++kk)
            p[kk] += __shfl_xor_sync(0xffffffffu, p[kk], s);

    float mx = p[0];
    #pragma unroll
    for (int kk = 1; kk < KT; ++kk) mx = fmaxf(mx, p[kk]);
    float e[KT], se = 0.f;
    #pragma unroll
    for (int kk = 0; kk < KT; ++kk) { e[kk] = __expf(p[kk] - mx); se += e[kk]; }
    float inv = 0.125f / se;             // includes /sqrt(HEAD_W)

    float4 a = make_float4(0.f, 0.f, 0.f, 0.f);
    #pragma unroll
    for (int kk = 0; kk < KT; ++kk) {
        a.x += e[kk] * vv[kk].x; a.y += e[kk] * vv[kk].y;
        a.z += e[kk] * vv[kk].z; a.w += e[kk] * vv[kk].w;
    }
    a.x *= inv; a.y *= inv; a.z *= inv; a.w *= inv;

    __half2 o01 = __floats2half2_rn(a.x, a.y);
    __half2 o23 = __floats2half2_rn(a.z, a.w);
    uint2 out; out.x = *(uint32_t*)&o01; out.y = *(uint32_t*)&o23;
    *(uint2*)(g_ATTN + (size_t)row * DM + qoff + e0) = out;
}

// ---------------------------------------------------------------------------
// Launch
// ---------------------------------------------------------------------------
extern "C" void kernel_launch(void* const* d_in, const int* in_sizes, int n_in,
                              void* d_out, int out_size) {
    const float* x   = (const float*)d_in[0];
    const float* q_w = (const float*)d_in[1];
    const float* q_b = (const float*)d_in[2];
    const float* k_w = (const float*)d_in[3];
    const float* k_b = (const float*)d_in[4];
    const float* v_w = (const float*)d_in[5];
    const float* v_b = (const float*)d_in[6];
    const float* o_w = (const float*)d_in[7];
    const float* o_b = (const float*)d_in[8];

    __half *Xh, *Wh, *OWh, *PV, *ATTN;
    float *PQK;
    cudaGetSymbolAddress((void**)&Xh,   g_Xh);
    cudaGetSymbolAddress((void**)&Wh,   g_Wh);
    cudaGetSymbolAddress((void**)&OWh,  g_OWh);
    cudaGetSymbolAddress((void**)&PQK,  g_PQK);
    cudaGetSymbolAddress((void**)&PV,   g_PV);
    cudaGetSymbolAddress((void**)&ATTN, g_ATTN);

    const int smem1 = NSTG * (128 + BN) * SKH * 2;   // 61440 B
    const int smem3 = NSTG * (64  + BN) * SKH * 2;   // 46080 B
    cudaFuncSetAttribute(gemm_fp16<128, NQK, false>,
                         cudaFuncAttributeMaxDynamicSharedMemorySize, smem1);
    cudaFuncSetAttribute(gemm_fp16<64, DM, true>,
                         cudaFuncAttributeMaxDynamicSharedMemorySize, smem3);

    // K0: convert to fp16 (vectorized)
    prep_kernel<<<(PREP4 + 255) / 256, 256>>>(x, q_w, k_w, v_w, o_w);

    // K1: cols 0..3071 -> PQK fp32, cols 3072..5631 -> PV fp16
    gemm_fp16<128, NQK, false><<<dim3(NTOT / BN, MTOT / 128), 256, smem1>>>(
        Xh, Wh, PQK, NQK, PV, NKV_, nullptr);

    // K2: attention -> ATTN[4096, 512] fp16  (warp = row x head-pair)
    attn_kernel<<<(MTOT * (HH / 2) * 32) / 256, 256>>>(q_b, k_b, v_b);

    // K3: OUT = ATTN @ OWh^T + o_b
    gemm_fp16<64, DM, true><<<dim3(DM / BN, MTOT / 64), 256, smem3>>>(
        ATTN, OWh, (float*)d_out, DM, (__half*)nullptr, 0, o_b);
}

// round 13
// speedup vs baseline: 1.3194x; 1.0961x over previous
#include <cuda_runtime.h>
#include <cuda_fp16.h>
#include <cstdint>

// ---------------------------------------------------------------------------
// Problem constants
// ---------------------------------------------------------------------------
#define BB   2
#define LL   2048
#define DM   512
#define HH   8
#define KT   5
#define HW   64
#define MTOT (BB*LL)                  // 4096
#define NKV_ (HH*KT*HW)               // 2560
#define NQK  (DM + NKV_)              // 3072  (q then k)
#define NTOT (NQK + NKV_)             // 5632
#define KBASE (DM)                    // k starts at col 512 in PQK
#define KD   512

// ---------------------------------------------------------------------------
// Device scratch
// ---------------------------------------------------------------------------
__device__ __half g_Xh  [(size_t)MTOT * KD];      //  4.2 MB
__device__ __half g_Wh  [(size_t)NTOT * KD];      //  5.8 MB [qw;kw;vw]
__device__ __half g_OWh [(size_t)DM * KD];        //  0.5 MB
__device__ float  g_PQK [(size_t)MTOT * NQK];     // 50.3 MB fp32 q,k projections
__device__ __half g_PV  [(size_t)MTOT * NKV_];    // 21.0 MB fp16 v projections
__device__ __half g_ATTN[(size_t)MTOT * DM];      //  4.2 MB

// ---------------------------------------------------------------------------
// Helpers
// ---------------------------------------------------------------------------
__device__ __forceinline__ void ldm_x4(uint32_t& r0, uint32_t& r1, uint32_t& r2, uint32_t& r3,
                                       const void* p) {
    uint32_t a = (uint32_t)__cvta_generic_to_shared(p);
    asm volatile("ldmatrix.sync.aligned.m8n8.x4.shared.b16 {%0,%1,%2,%3}, [%4];"
                 : "=r"(r0), "=r"(r1), "=r"(r2), "=r"(r3) : "r"(a));
}

__device__ __forceinline__ void mma_fp16(float d[4], const uint32_t a[4], const uint32_t b[2]) {
    asm volatile(
        "mma.sync.aligned.m16n8k16.row.col.f32.f16.f16.f32 "
        "{%0,%1,%2,%3}, {%4,%5,%6,%7}, {%8,%9}, {%0,%1,%2,%3};\n"
        : "+f"(d[0]), "+f"(d[1]), "+f"(d[2]), "+f"(d[3])
        : "r"(a[0]), "r"(a[1]), "r"(a[2]), "r"(a[3]), "r"(b[0]), "r"(b[1]));
}

#define CP_ASYNC16(smem_ptr, gptr) \
    asm volatile("cp.async.cg.shared.global [%0], [%1], 16;\n" \
                 :: "r"((uint32_t)__cvta_generic_to_shared(smem_ptr)), "l"(gptr))

// ---------------------------------------------------------------------------
// K0: convert inputs to fp16, float4-vectorized
// ---------------------------------------------------------------------------
#define NX_  (MTOT*KD)
#define NQW_ (DM*KD)
#define NKW_ (NKV_*KD)
#define NW_  (NQW_ + 2*NKW_)
#define NX4  (NX_/4)
#define NQW4 (NQW_/4)
#define NKW4 (NKW_/4)
#define NW4  (NW_/4)
#define PREP4 (NX4 + NW4 + NQW4)

__device__ __forceinline__ void cvt4(__half* dst, float4 f) {
    __half2* d2 = (__half2*)dst;
    d2[0] = __floats2half2_rn(f.x, f.y);
    d2[1] = __floats2half2_rn(f.z, f.w);
}

__global__ void prep_kernel(const float* __restrict__ x,
                            const float* __restrict__ qw,
                            const float* __restrict__ kw,
                            const float* __restrict__ vw,
                            const float* __restrict__ ow) {
    int i = blockIdx.x * blockDim.x + threadIdx.x;
    if (i >= PREP4) return;
    if (i < NX4) {
        cvt4(g_Xh + 4 * (size_t)i, ((const float4*)x)[i]);
    } else {
        int j = i - NX4;
        if (j < NW4) {
            float4 f;
            if (j < NQW4)            f = ((const float4*)qw)[j];
            else if (j < NQW4+NKW4)  f = ((const float4*)kw)[j - NQW4];
            else                     f = ((const float4*)vw)[j - NQW4 - NKW4];
            cvt4(g_Wh + 4 * (size_t)j, f);
        } else {
            int p = j - NW4;
            cvt4(g_OWh + 4 * (size_t)p, ((const float4*)ow)[p]);
        }
    }
}

// ---------------------------------------------------------------------------
// fp16 GEMM: BK=64 (8 barriers/tile instead of 16), 3-stage cp.async,
// single __syncthreads per K-iter, cp.async issued inside chunk-0's LDSM
// latency window. CTA BMt x 128, 8 warps (2x4), warp tile (BMt/2) x 32.
// smem stride 72 fp16 (144 B): rows cover 8 distinct 16B segments =>
// conflict-free ldmatrix. Mixed output: n0 < NSPLIT -> fp32, else fp16.
// ---------------------------------------------------------------------------
#define BN  128
#define BKH 64
#define SKH 72
#define NSTG 3

template <int BMt, int NSPLIT, bool HAS_BIAS>
__global__ __launch_bounds__(256, 2) void gemm_fp16(
    const __half* __restrict__ A, const __half* __restrict__ B,
    float* __restrict__ C32, int ldc32,
    __half* __restrict__ C16, int ldc16,
    const float* __restrict__ bias)
{
    extern __shared__ __half sh[];
    const int STG = (BMt + BN) * SKH;
    constexpr int MT = BMt / 32;

    const int n0  = blockIdx.x * BN;
    const int m0  = blockIdx.y * BMt;
    const int tid = threadIdx.x;
    const int warp = tid >> 5, lane = tid & 31;
    const int wm = (warp >> 2) * (16 * MT);
    const int wn = (warp & 3) * 32;
    const int g  = lane >> 2, t = lane & 3;

    float acc[MT][4][4];
    #pragma unroll
    for (int mt = 0; mt < MT; mt++)
        #pragma unroll
        for (int nt = 0; nt < 4; nt++)
            #pragma unroll
            for (int i = 0; i < 4; i++) acc[mt][nt][i] = 0.f;

    const __half* Ab = A + (size_t)m0 * KD;
    const __half* Bb = B + (size_t)n0 * KD;

    // Stage row = 64 halfs = 128 B = 8 x 16B chunks. r = idx>>3, c = (idx&7)*8.
    auto load_stage = [&](int s, int k0) {
        __half* as = sh + (s % NSTG) * STG;
        __half* bs = as + BMt * SKH;
        #pragma unroll
        for (int i = 0; i < BMt / 32; ++i) {     // BMt*8 chunks of A
            int idx = tid + 256 * i;
            int r = idx >> 3, c = (idx & 7) * 8;
            CP_ASYNC16(&as[r * SKH + c], Ab + (size_t)r * KD + k0 + c);
        }
        #pragma unroll
        for (int i = 0; i < 4; ++i) {            // 1024 chunks of B (128 rows)
            int idx = tid + 256 * i;
            int r = idx >> 3, c = (idx & 7) * 8;
            CP_ASYNC16(&bs[r * SKH + c], Bb + (size_t)r * KD + k0 + c);
        }
        asm volatile("cp.async.commit_group;\n" ::);
    };

    const int NKt = KD / BKH;   // 8
    load_stage(0, 0);
    load_stage(1, BKH);

    const int rowA  = lane & 15;
    const int kselA = ((lane >> 4) & 1) * 8;
    const int rowB  = lane & 7;
    const int nselB = ((lane >> 4) & 1) * 8;
    const int kselB = ((lane >> 3) & 1) * 8;

    auto ldsm_frags = [&](const __half* as, const __half* bs, int kb,
                          uint32_t af[][4], uint32_t bf[][2]) {
        #pragma unroll
        for (int mt = 0; mt < MT; mt++)
            ldm_x4(af[mt][0], af[mt][1], af[mt][2], af[mt][3],
                   &as[(wm + mt * 16 + rowA) * SKH + kb + kselA]);
        #pragma unroll
        for (int p = 0; p < 2; p++)
            ldm_x4(bf[2*p][0], bf[2*p][1], bf[2*p+1][0], bf[2*p+1][1],
                   &bs[(wn + p * 16 + nselB + rowB) * SKH + kb + kselB]);
    };

    auto mma_block = [&](uint32_t af[][4], uint32_t bf[][2]) {
        #pragma unroll
        for (int mt = 0; mt < MT; mt++)
            #pragma unroll
            for (int nt = 0; nt < 4; nt++)
                mma_fp16(acc[mt][nt], af[mt], bf[nt]);
    };

    for (int kt = 0; kt < NKt; ++kt) {
        if (kt + 1 < NKt) asm volatile("cp.async.wait_group 1;\n" ::);
        else              asm volatile("cp.async.wait_group 0;\n" ::);
        __syncthreads();               // single barrier per iteration

        const __half* as = sh + (kt % NSTG) * STG;
        const __half* bs = as + BMt * SKH;

        uint32_t af[MT][4], bf[4][2];
        // chunk 0 LDSMs first; cp.async burst fills their latency window
        ldsm_frags(as, bs, 0, af, bf);
        if (kt + 2 < NKt) load_stage(kt + 2, (kt + 2) * BKH);
        mma_block(af, bf);
        #pragma unroll
        for (int ch = 1; ch < 4; ++ch) {
            ldsm_frags(as, bs, ch * 16, af, bf);
            mma_block(af, bf);
        }
    }

    const bool f32out = (n0 < NSPLIT);
    #pragma unroll
    for (int mt = 0; mt < MT; mt++) {
        int r = m0 + wm + mt * 16 + g;
        #pragma unroll
        for (int nt = 0; nt < 4; nt++) {
            int c = n0 + wn + nt * 8 + 2 * t;
            float o0 = acc[mt][nt][0], o1 = acc[mt][nt][1];
            float o2 = acc[mt][nt][2], o3 = acc[mt][nt][3];
            if (HAS_BIAS) {
                float b0 = bias[c], b1 = bias[c + 1];
                o0 += b0; o1 += b1; o2 += b0; o3 += b1;
            }
            if (f32out) {
                *(float2*)&C32[(size_t)(r    ) * ldc32 + c] = make_float2(o0, o1);
                *(float2*)&C32[(size_t)(r + 8) * ldc32 + c] = make_float2(o2, o3);
            } else {
                int c16 = c - NSPLIT;
                *(__half2*)&C16[(size_t)(r    ) * ldc16 + c16] = __floats2half2_rn(o0, o1);
                *(__half2*)&C16[(size_t)(r + 8) * ldc16 + c16] = __floats2half2_rn(o2, o3);
            }
        }
    }
}

// ---------------------------------------------------------------------------
// K2: attention (round-12 winner). Warp = (row, head-pair), 16 lanes/head,
// float4 gathers, 5 pipelined width-16 reductions, softmax, V mix.
// ---------------------------------------------------------------------------
__global__ __launch_bounds__(256) void attn_kernel(const float* __restrict__ qb,
                                                   const float* __restrict__ kb,
                                                   const float* __restrict__ vb) {
    int w    = (blockIdx.x * blockDim.x + threadIdx.x) >> 5;
    int lane = threadIdx.x & 31;
    if (w >= MTOT * (HH / 2)) return;

    int hp  = w & 3;
    int row = w >> 2;
    int l   = row & (LL - 1);
    int b   = row >> 11;
    int h   = hp * 2 + (lane >> 4);
    int li  = lane & 15;
    int d   = 1 << (h & 3);

    const float4* QK4 = (const float4*)g_PQK;
    const int NQK4 = NQK / 4;
    int qoff = h * HW;
    int e0   = li * 4;

    float4 q = QK4[(size_t)row * NQK4 + ((qoff + e0) >> 2)];
    {
        float4 qb4 = ((const float4*)qb)[(qoff + e0) >> 2];
        q.x += qb4.x; q.y += qb4.y; q.z += qb4.z; q.w += qb4.w;
    }

    float  p[KT];
    float4 vv[KT];
    #pragma unroll
    for (int kk = 0; kk < KT; ++kk) {
        int sl   = l + (kk - 2) * d;
        int kidx = (h * KT + kk) * HW + e0;
        float4 kb4 = ((const float4*)kb)[kidx >> 2];
        float4 vb4 = ((const float4*)vb)[kidx >> 2];
        float4 kf, vf;
        if (sl >= 0 && sl < LL) {
            int srow = b * LL + sl;
            kf = QK4[(size_t)srow * NQK4 + ((KBASE + kidx) >> 2)];
            uint2 vraw = *(const uint2*)(g_PV + (size_t)srow * NKV_ + kidx);
            __half2 v01 = *(__half2*)&vraw.x, v23 = *(__half2*)&vraw.y;
            float2 f01 = __half22float2(v01), f23 = __half22float2(v23);
            kf.x += kb4.x; kf.y += kb4.y; kf.z += kb4.z; kf.w += kb4.w;
            vf = make_float4(f01.x + vb4.x, f01.y + vb4.y,
                             f23.x + vb4.z, f23.y + vb4.w);
        } else {
            kf = kb4;
            vf = vb4;
        }
        vv[kk] = vf;
        p[kk] = q.x * kf.x + q.y * kf.y + q.z * kf.z + q.w * kf.w;
    }

    #pragma unroll
    for (int s = 8; s > 0; s >>= 1)
        #pragma unroll
        for (int kk = 0; kk < KT; ++kk)
            p[kk] += __shfl_xor_sync(0xffffffffu, p[kk], s);

    float mx = p[0];
    #pragma unroll
    for (int kk = 1; kk < KT; ++kk) mx = fmaxf(mx, p[kk]);
    float e[KT], se = 0.f;
    #pragma unroll
    for (int kk = 0; kk < KT; ++kk) { e[kk] = __expf(p[kk] - mx); se += e[kk]; }
    float inv = 0.125f / se;

    float4 a = make_float4(0.f, 0.f, 0.f, 0.f);
    #pragma unroll
    for (int kk = 0; kk < KT; ++kk) {
        a.x += e[kk] * vv[kk].x; a.y += e[kk] * vv[kk].y;
        a.z += e[kk] * vv[kk].z; a.w += e[kk] * vv[kk].w;
    }
    a.x *= inv; a.y *= inv; a.z *= inv; a.w *= inv;

    __half2 o01 = __floats2half2_rn(a.x, a.y);
    __half2 o23 = __floats2half2_rn(a.z, a.w);
    uint2 out; out.x = *(uint32_t*)&o01; out.y = *(uint32_t*)&o23;
    *(uint2*)(g_ATTN + (size_t)row * DM + qoff + e0) = out;
}

// ---------------------------------------------------------------------------
// Launch
// ---------------------------------------------------------------------------
extern "C" void kernel_launch(void* const* d_in, const int* in_sizes, int n_in,
                              void* d_out, int out_size) {
    const float* x   = (const float*)d_in[0];
    const float* q_w = (const float*)d_in[1];
    const float* q_b = (const float*)d_in[2];
    const float* k_w = (const float*)d_in[3];
    const float* k_b = (const float*)d_in[4];
    const float* v_w = (const float*)d_in[5];
    const float* v_b = (const float*)d_in[6];
    const float* o_w = (const float*)d_in[7];
    const float* o_b = (const float*)d_in[8];

    __half *Xh, *Wh, *OWh, *PV, *ATTN;
    float *PQK;
    cudaGetSymbolAddress((void**)&Xh,   g_Xh);
    cudaGetSymbolAddress((void**)&Wh,   g_Wh);
    cudaGetSymbolAddress((void**)&OWh,  g_OWh);
    cudaGetSymbolAddress((void**)&PQK,  g_PQK);
    cudaGetSymbolAddress((void**)&PV,   g_PV);
    cudaGetSymbolAddress((void**)&ATTN, g_ATTN);

    const int smem1 = NSTG * (128 + BN) * SKH * 2;   // 110592 B
    const int smem3 = NSTG * (64  + BN) * SKH * 2;   //  82944 B
    cudaFuncSetAttribute(gemm_fp16<128, NQK, false>,
                         cudaFuncAttributeMaxDynamicSharedMemorySize, smem1);
    cudaFuncSetAttribute(gemm_fp16<64, DM, true>,
                         cudaFuncAttributeMaxDynamicSharedMemorySize, smem3);

    // K0: convert to fp16 (vectorized)
    prep_kernel<<<(PREP4 + 255) / 256, 256>>>(x, q_w, k_w, v_w, o_w);

    // K1: cols 0..3071 -> PQK fp32, cols 3072..5631 -> PV fp16
    gemm_fp16<128, NQK, false><<<dim3(NTOT / BN, MTOT / 128), 256, smem1>>>(
        Xh, Wh, PQK, NQK, PV, NKV_, nullptr);

    // K2: attention -> ATTN[4096, 512] fp16
    attn_kernel<<<(MTOT * (HH / 2) * 32) / 256, 256>>>(q_b, k_b, v_b);

    // K3: OUT = ATTN @ OWh^T + o_b
    gemm_fp16<64, DM, true><<<dim3(DM / BN, MTOT / 64), 256, smem3>>>(
        ATTN, OWh, (float*)d_out, DM, (__half*)nullptr, 0, o_b);
}

// round 15
// speedup vs baseline: 1.3516x; 1.0244x over previous
// Resubmit of round-14 kernel (broker container failure — no execution data).
#include <cuda_runtime.h>
#include <cuda_fp16.h>
#include <cstdint>

// ---------------------------------------------------------------------------
// Problem constants
// ---------------------------------------------------------------------------
#define BB   2
#define LL   2048
#define DM   512
#define HH   8
#define KT   5
#define HW   64
#define MTOT (BB*LL)                  // 4096
#define NKV_ (HH*KT*HW)               // 2560
#define NQK  (DM + NKV_)              // 3072  (q then k)
#define NTOT (NQK + NKV_)             // 5632
#define KBASE (DM)                    // k starts at col 512 in PQK
#define KD   512

// ---------------------------------------------------------------------------
// Device scratch
// ---------------------------------------------------------------------------
__device__ __half g_Xh  [(size_t)MTOT * KD];      //  4.2 MB
__device__ __half g_Wh  [(size_t)NTOT * KD];      //  5.8 MB [qw;kw;vw]
__device__ __half g_OWh [(size_t)DM * KD];        //  0.5 MB
__device__ float  g_PQK [(size_t)MTOT * NQK];     // 50.3 MB fp32 q,k projections
__device__ __half g_PV  [(size_t)MTOT * NKV_];    // 21.0 MB fp16 v projections
__device__ __half g_ATTN[(size_t)MTOT * DM];      //  4.2 MB

// ---------------------------------------------------------------------------
// Helpers
// ---------------------------------------------------------------------------
__device__ __forceinline__ void ldm_x4(uint32_t& r0, uint32_t& r1, uint32_t& r2, uint32_t& r3,
                                       const void* p) {
    uint32_t a = (uint32_t)__cvta_generic_to_shared(p);
    asm volatile("ldmatrix.sync.aligned.m8n8.x4.shared.b16 {%0,%1,%2,%3}, [%4];"
                 : "=r"(r0), "=r"(r1), "=r"(r2), "=r"(r3) : "r"(a));
}

__device__ __forceinline__ void mma_fp16(float d[4], const uint32_t a[4], const uint32_t b[2]) {
    asm volatile(
        "mma.sync.aligned.m16n8k16.row.col.f32.f16.f16.f32 "
        "{%0,%1,%2,%3}, {%4,%5,%6,%7}, {%8,%9}, {%0,%1,%2,%3};\n"
        : "+f"(d[0]), "+f"(d[1]), "+f"(d[2]), "+f"(d[3])
        : "r"(a[0]), "r"(a[1]), "r"(a[2]), "r"(a[3]), "r"(b[0]), "r"(b[1]));
}

#define CP_ASYNC16(smem_ptr, gptr) \
    asm volatile("cp.async.cg.shared.global [%0], [%1], 16;\n" \
                 :: "r"((uint32_t)__cvta_generic_to_shared(smem_ptr)), "l"(gptr))

// ---------------------------------------------------------------------------
// K0: convert inputs to fp16, float4-vectorized
// ---------------------------------------------------------------------------
#define NX_  (MTOT*KD)
#define NQW_ (DM*KD)
#define NKW_ (NKV_*KD)
#define NW_  (NQW_ + 2*NKW_)
#define NX4  (NX_/4)
#define NQW4 (NQW_/4)
#define NKW4 (NKW_/4)
#define NW4  (NW_/4)
#define PREP4 (NX4 + NW4 + NQW4)

__device__ __forceinline__ void cvt4(__half* dst, float4 f) {
    __half2* d2 = (__half2*)dst;
    d2[0] = __floats2half2_rn(f.x, f.y);
    d2[1] = __floats2half2_rn(f.z, f.w);
}

__global__ void prep_kernel(const float* __restrict__ x,
                            const float* __restrict__ qw,
                            const float* __restrict__ kw,
                            const float* __restrict__ vw,
                            const float* __restrict__ ow) {
    int i = blockIdx.x * blockDim.x + threadIdx.x;
    if (i >= PREP4) return;
    if (i < NX4) {
        cvt4(g_Xh + 4 * (size_t)i, ((const float4*)x)[i]);
    } else {
        int j = i - NX4;
        if (j < NW4) {
            float4 f;
            if (j < NQW4)            f = ((const float4*)qw)[j];
            else if (j < NQW4+NKW4)  f = ((const float4*)kw)[j - NQW4];
            else                     f = ((const float4*)vw)[j - NQW4 - NKW4];
            cvt4(g_Wh + 4 * (size_t)j, f);
        } else {
            int p = j - NW4;
            cvt4(g_OWh + 4 * (size_t)p, ((const float4*)ow)[p]);
        }
    }
}

// ---------------------------------------------------------------------------
// fp16 GEMM: CTA 64x128, 8 warps (2x4), warp tile 32x32, BK=64.
// Rows are exactly 128 B with SW128 XOR swizzle (no padding) =>
// 3-stage footprint 73.7 KB => 3 CTAs/SM = 24 warps (__launch_bounds(256,3)).
// 3-stage cp.async, single __syncthreads per K-iter, cp.async burst issued
// inside chunk-0's LDSM latency window. Mixed out: n0 < NSPLIT fp32 else fp16.
// ---------------------------------------------------------------------------
#define BMt 64
#define BN  128
#define BKH 64
#define NSTG 3
#define ROWB 128                       // bytes per smem row (64 fp16)
#define STGB ((BMt + BN) * ROWB)       // 24576 B per stage
#define SWZ(r, cb) ((cb) ^ (((r) & 7) << 4))

template <int NSPLIT, bool HAS_BIAS>
__global__ __launch_bounds__(256, 3) void gemm_fp16(
    const __half* __restrict__ A, const __half* __restrict__ B,
    float* __restrict__ C32, int ldc32,
    __half* __restrict__ C16, int ldc16,
    const float* __restrict__ bias)
{
    extern __shared__ char shb[];

    const int n0  = blockIdx.x * BN;
    const int m0  = blockIdx.y * BMt;
    const int tid = threadIdx.x;
    const int warp = tid >> 5, lane = tid & 31;
    const int wm = (warp >> 2) * 32;     // 0, 32
    const int wn = (warp & 3) * 32;      // 0, 32, 64, 96
    const int g  = lane >> 2, t = lane & 3;

    float acc[2][4][4];
    #pragma unroll
    for (int mt = 0; mt < 2; mt++)
        #pragma unroll
        for (int nt = 0; nt < 4; nt++)
            #pragma unroll
            for (int i = 0; i < 4; i++) acc[mt][nt][i] = 0.f;

    const __half* Ab = A + (size_t)m0 * KD;
    const __half* Bb = B + (size_t)n0 * KD;

    // Stage row = 128 B = 8 x 16B chunks; dest col swizzled by row.
    auto load_stage = [&](int s, int k0) {
        char* as = shb + (s % NSTG) * STGB;
        char* bs = as + BMt * ROWB;
        #pragma unroll
        for (int i = 0; i < 2; ++i) {            // A: 512 chunks (64 rows)
            int idx = tid + 256 * i;
            int r = idx >> 3, cb = (idx & 7) * 16;
            CP_ASYNC16(as + r * ROWB + SWZ(r, cb), Ab + (size_t)r * KD + k0 + (idx & 7) * 8);
        }
        #pragma unroll
        for (int i = 0; i < 4; ++i) {            // B: 1024 chunks (128 rows)
            int idx = tid + 256 * i;
            int r = idx >> 3, cb = (idx & 7) * 16;
            CP_ASYNC16(bs + r * ROWB + SWZ(r, cb), Bb + (size_t)r * KD + k0 + (idx & 7) * 8);
        }
        asm volatile("cp.async.commit_group;\n" ::);
    };

    const int NKt = KD / BKH;   // 8
    load_stage(0, 0);
    load_stage(1, BKH);

    // ldmatrix lane->row/col (bytes)
    const int rowA  = lane & 15;
    const int selA  = ((lane >> 4) & 1) * 16;    // 16B toggle within k-chunk
    const int rowB  = lane & 7;
    const int nselB = ((lane >> 4) & 1) * 8;
    const int selB  = ((lane >> 3) & 1) * 16;

    auto ldsm_frags = [&](const char* as, const char* bs, int kb2,
                          uint32_t af[][4], uint32_t bf[][2]) {
        #pragma unroll
        for (int mt = 0; mt < 2; mt++) {
            int r = wm + mt * 16 + rowA;
            ldm_x4(af[mt][0], af[mt][1], af[mt][2], af[mt][3],
                   as + r * ROWB + SWZ(r, kb2 + selA));
        }
        #pragma unroll
        for (int p = 0; p < 2; p++) {
            int r = wn + p * 16 + nselB + rowB;
            ldm_x4(bf[2*p][0], bf[2*p][1], bf[2*p+1][0], bf[2*p+1][1],
                   bs + r * ROWB + SWZ(r, kb2 + selB));
        }
    };

    auto mma_block = [&](uint32_t af[][4], uint32_t bf[][2]) {
        #pragma unroll
        for (int mt = 0; mt < 2; mt++)
            #pragma unroll
            for (int nt = 0; nt < 4; nt++)
                mma_fp16(acc[mt][nt], af[mt], bf[nt]);
    };

    for (int kt = 0; kt < NKt; ++kt) {
        if (kt + 1 < NKt) asm volatile("cp.async.wait_group 1;\n" ::);
        else              asm volatile("cp.async.wait_group 0;\n" ::);
        __syncthreads();                         // single barrier per iter

        const char* as = shb + (kt % NSTG) * STGB;
        const char* bs = as + BMt * ROWB;

        uint32_t af[2][4], bf[4][2];
        ldsm_frags(as, bs, 0, af, bf);           // chunk 0
        if (kt + 2 < NKt) load_stage(kt + 2, (kt + 2) * BKH);
        mma_block(af, bf);
        #pragma unroll
        for (int ch = 1; ch < 4; ++ch) {         // chunks 1..3 (32 B apart)
            ldsm_frags(as, bs, ch * 32, af, bf);
            mma_block(af, bf);
        }
    }

    const bool f32out = (n0 < NSPLIT);
    #pragma unroll
    for (int mt = 0; mt < 2; mt++) {
        int r = m0 + wm + mt * 16 + g;
        #pragma unroll
        for (int nt = 0; nt < 4; nt++) {
            int c = n0 + wn + nt * 8 + 2 * t;
            float o0 = acc[mt][nt][0], o1 = acc[mt][nt][1];
            float o2 = acc[mt][nt][2], o3 = acc[mt][nt][3];
            if (HAS_BIAS) {
                float b0 = bias[c], b1 = bias[c + 1];
                o0 += b0; o1 += b1; o2 += b0; o3 += b1;
            }
            if (f32out) {
                *(float2*)&C32[(size_t)(r    ) * ldc32 + c] = make_float2(o0, o1);
                *(float2*)&C32[(size_t)(r + 8) * ldc32 + c] = make_float2(o2, o3);
            } else {
                int c16 = c - NSPLIT;
                *(__half2*)&C16[(size_t)(r    ) * ldc16 + c16] = __floats2half2_rn(o0, o1);
                *(__half2*)&C16[(size_t)(r + 8) * ldc16 + c16] = __floats2half2_rn(o2, o3);
            }
        }
    }
}

// ---------------------------------------------------------------------------
// K2: attention (round-12 winner). Warp = (row, head-pair), 16 lanes/head,
// float4 gathers, 5 pipelined width-16 reductions, softmax, V mix.
// ---------------------------------------------------------------------------
__global__ __launch_bounds__(256) void attn_kernel(const float* __restrict__ qb,
                                                   const float* __restrict__ kb,
                                                   const float* __restrict__ vb) {
    int w    = (blockIdx.x * blockDim.x + threadIdx.x) >> 5;
    int lane = threadIdx.x & 31;
    if (w >= MTOT * (HH / 2)) return;

    int hp  = w & 3;
    int row = w >> 2;
    int l   = row & (LL - 1);
    int b   = row >> 11;
    int h   = hp * 2 + (lane >> 4);
    int li  = lane & 15;
    int d   = 1 << (h & 3);

    const float4* QK4 = (const float4*)g_PQK;
    const int NQK4 = NQK / 4;
    int qoff = h * HW;
    int e0   = li * 4;

    float4 q = QK4[(size_t)row * NQK4 + ((qoff + e0) >> 2)];
    {
        float4 qb4 = ((const float4*)qb)[(qoff + e0) >> 2];
        q.x += qb4.x; q.y += qb4.y; q.z += qb4.z; q.w += qb4.w;
    }

    float  p[KT];
    float4 vv[KT];
    #pragma unroll
    for (int kk = 0; kk < KT; ++kk) {
        int sl   = l + (kk - 2) * d;
        int kidx = (h * KT + kk) * HW + e0;
        float4 kb4 = ((const float4*)kb)[kidx >> 2];
        float4 vb4 = ((const float4*)vb)[kidx >> 2];
        float4 kf, vf;
        if (sl >= 0 && sl < LL) {
            int srow = b * LL + sl;
            kf = QK4[(size_t)srow * NQK4 + ((KBASE + kidx) >> 2)];
            uint2 vraw = *(const uint2*)(g_PV + (size_t)srow * NKV_ + kidx);
            __half2 v01 = *(__half2*)&vraw.x, v23 = *(__half2*)&vraw.y;
            float2 f01 = __half22float2(v01), f23 = __half22float2(v23);
            kf.x += kb4.x; kf.y += kb4.y; kf.z += kb4.z; kf.w += kb4.w;
            vf = make_float4(f01.x + vb4.x, f01.y + vb4.y,
                             f23.x + vb4.z, f23.y + vb4.w);
        } else {
            kf = kb4;
            vf = vb4;
        }
        vv[kk] = vf;
        p[kk] = q.x * kf.x + q.y * kf.y + q.z * kf.z + q.w * kf.w;
    }

    #pragma unroll
    for (int s = 8; s > 0; s >>= 1)
        #pragma unroll
        for (int kk = 0; kk < KT; ++kk)
            p[kk] += __shfl_xor_sync(0xffffffffu, p[kk], s);

    float mx = p[0];
    #pragma unroll
    for (int kk = 1; kk < KT; ++kk) mx = fmaxf(mx, p[kk]);
    float e[KT], se = 0.f;
    #pragma unroll
    for (int kk = 0; kk < KT; ++kk) { e[kk] = __expf(p[kk] - mx); se += e[kk]; }
    float inv = 0.125f / se;

    float4 a = make_float4(0.f, 0.f, 0.f, 0.f);
    #pragma unroll
    for (int kk = 0; kk < KT; ++kk) {
        a.x += e[kk] * vv[kk].x; a.y += e[kk] * vv[kk].y;
        a.z += e[kk] * vv[kk].z; a.w += e[kk] * vv[kk].w;
    }
    a.x *= inv; a.y *= inv; a.z *= inv; a.w *= inv;

    __half2 o01 = __floats2half2_rn(a.x, a.y);
    __half2 o23 = __floats2half2_rn(a.z, a.w);
    uint2 out; out.x = *(uint32_t*)&o01; out.y = *(uint32_t*)&o23;
    *(uint2*)(g_ATTN + (size_t)row * DM + qoff + e0) = out;
}

// ---------------------------------------------------------------------------
// Launch
// ---------------------------------------------------------------------------
extern "C" void kernel_launch(void* const* d_in, const int* in_sizes, int n_in,
                              void* d_out, int out_size) {
    const float* x   = (const float*)d_in[0];
    const float* q_w = (const float*)d_in[1];
    const float* q_b = (const float*)d_in[2];
    const float* k_w = (const float*)d_in[3];
    const float* k_b = (const float*)d_in[4];
    const float* v_w = (const float*)d_in[5];
    const float* v_b = (const float*)d_in[6];
    const float* o_w = (const float*)d_in[7];
    const float* o_b = (const float*)d_in[8];

    __half *Xh, *Wh, *OWh, *PV, *ATTN;
    float *PQK;
    cudaGetSymbolAddress((void**)&Xh,   g_Xh);
    cudaGetSymbolAddress((void**)&Wh,   g_Wh);
    cudaGetSymbolAddress((void**)&OWh,  g_OWh);
    cudaGetSymbolAddress((void**)&PQK,  g_PQK);
    cudaGetSymbolAddress((void**)&PV,   g_PV);
    cudaGetSymbolAddress((void**)&ATTN, g_ATTN);

    const int smem = NSTG * STGB;                    // 73728 B
    cudaFuncSetAttribute(gemm_fp16<NQK, false>,
                         cudaFuncAttributeMaxDynamicSharedMemorySize, smem);
    cudaFuncSetAttribute(gemm_fp16<DM, true>,
                         cudaFuncAttributeMaxDynamicSharedMemorySize, smem);

    // K0: convert to fp16 (vectorized)
    prep_kernel<<<(PREP4 + 255) / 256, 256>>>(x, q_w, k_w, v_w, o_w);

    // K1: cols 0..3071 -> PQK fp32, cols 3072..5631 -> PV fp16
    gemm_fp16<NQK, false><<<dim3(NTOT / BN, MTOT / BMt), 256, smem>>>(
        Xh, Wh, PQK, NQK, PV, NKV_, nullptr);

    // K2: attention -> ATTN[4096, 512] fp16
    attn_kernel<<<(MTOT * (HH / 2) * 32) / 256, 256>>>(q_b, k_b, v_b);

    // K3: OUT = ATTN @ OWh^T + o_b
    gemm_fp16<DM, true><<<dim3(DM / BN, MTOT / BMt), 256, smem>>>(
        ATTN, OWh, (float*)d_out, DM, (__half*)nullptr, 0, o_b);
}

// round 16
// speedup vs baseline: 1.3942x; 1.0315x over previous
#include <cuda_runtime.h>
#include <cuda_fp16.h>
#include <cstdint>

// ---------------------------------------------------------------------------
// Problem constants
// ---------------------------------------------------------------------------
#define BB   2
#define LL   2048
#define DM   512
#define HH   8
#define KT   5
#define HW   64
#define MTOT (BB*LL)                  // 4096
#define NKV_ (HH*KT*HW)               // 2560
#define NQK  (DM + NKV_)              // 3072  (q then k)
#define NTOT (NQK + NKV_)             // 5632
#define KBASE (DM)                    // k starts at col 512 in PQK
#define KD   512

// ---------------------------------------------------------------------------
// Device scratch
// ---------------------------------------------------------------------------
__device__ __half g_Xh  [(size_t)MTOT * KD];      //  4.2 MB
__device__ __half g_Wh  [(size_t)NTOT * KD];      //  5.8 MB [qw;kw;vw]
__device__ __half g_OWh [(size_t)DM * KD];        //  0.5 MB
__device__ float  g_PQK [(size_t)MTOT * NQK];     // 50.3 MB fp32 q,k projections
__device__ __half g_PV  [(size_t)MTOT * NKV_];    // 21.0 MB fp16 v projections
__device__ __half g_ATTN[(size_t)MTOT * DM];      //  4.2 MB

// ---------------------------------------------------------------------------
// Helpers
// ---------------------------------------------------------------------------
__device__ __forceinline__ void ldm_x4(uint32_t& r0, uint32_t& r1, uint32_t& r2, uint32_t& r3,
                                       const void* p) {
    uint32_t a = (uint32_t)__cvta_generic_to_shared(p);
    asm volatile("ldmatrix.sync.aligned.m8n8.x4.shared.b16 {%0,%1,%2,%3}, [%4];"
                 : "=r"(r0), "=r"(r1), "=r"(r2), "=r"(r3) : "r"(a));
}

__device__ __forceinline__ void mma_fp16(float d[4], const uint32_t a[4], const uint32_t b[2]) {
    asm volatile(
        "mma.sync.aligned.m16n8k16.row.col.f32.f16.f16.f32 "
        "{%0,%1,%2,%3}, {%4,%5,%6,%7}, {%8,%9}, {%0,%1,%2,%3};\n"
        : "+f"(d[0]), "+f"(d[1]), "+f"(d[2]), "+f"(d[3])
        : "r"(a[0]), "r"(a[1]), "r"(a[2]), "r"(a[3]), "r"(b[0]), "r"(b[1]));
}

#define CP_ASYNC16(smem_ptr, gptr) \
    asm volatile("cp.async.cg.shared.global [%0], [%1], 16;\n" \
                 :: "r"((uint32_t)__cvta_generic_to_shared(smem_ptr)), "l"(gptr))

// ---------------------------------------------------------------------------
// K0: convert inputs to fp16, float4-vectorized
// ---------------------------------------------------------------------------
#define NX_  (MTOT*KD)
#define NQW_ (DM*KD)
#define NKW_ (NKV_*KD)
#define NW_  (NQW_ + 2*NKW_)
#define NX4  (NX_/4)
#define NQW4 (NQW_/4)
#define NKW4 (NKW_/4)
#define NW4  (NW_/4)
#define PREP4 (NX4 + NW4 + NQW4)

__device__ __forceinline__ void cvt4(__half* dst, float4 f) {
    __half2* d2 = (__half2*)dst;
    d2[0] = __floats2half2_rn(f.x, f.y);
    d2[1] = __floats2half2_rn(f.z, f.w);
}

__global__ void prep_kernel(const float* __restrict__ x,
                            const float* __restrict__ qw,
                            const float* __restrict__ kw,
                            const float* __restrict__ vw,
                            const float* __restrict__ ow) {
    int i = blockIdx.x * blockDim.x + threadIdx.x;
    if (i >= PREP4) return;
    if (i < NX4) {
        cvt4(g_Xh + 4 * (size_t)i, ((const float4*)x)[i]);
    } else {
        int j = i - NX4;
        if (j < NW4) {
            float4 f;
            if (j < NQW4)            f = ((const float4*)qw)[j];
            else if (j < NQW4+NKW4)  f = ((const float4*)kw)[j - NQW4];
            else                     f = ((const float4*)vw)[j - NQW4 - NKW4];
            cvt4(g_Wh + 4 * (size_t)j, f);
        } else {
            int p = j - NW4;
            cvt4(g_OWh + 4 * (size_t)p, ((const float4*)ow)[p]);
        }
    }
}

// ---------------------------------------------------------------------------
// fp16 GEMM: CTA BMt x 128, 8 warps (2x4), warp tile (BMt/2) x 32, BK=64.
// SW128 XOR-swizzled rows of exactly 128 B (no padding). 3-stage cp.async,
// single __syncthreads per K-iter. FRAGMENT DOUBLE-BUFFERING: chunk ch+1's
// LDSMs issue before chunk ch's MMAs, hiding LDSM latency inside the warp.
// Mixed output: n0 < NSPLIT -> fp32 C32, else fp16 C16.
// ---------------------------------------------------------------------------
#define BN  128
#define BKH 64
#define NSTG 3
#define ROWB 128                       // bytes per smem row (64 fp16)
#define SWZ(r, cb) ((cb) ^ (((r) & 7) << 4))

template <int BMt, int NSPLIT, bool HAS_BIAS>
__global__ __launch_bounds__(256, 2) void gemm_fp16(
    const __half* __restrict__ A, const __half* __restrict__ B,
    float* __restrict__ C32, int ldc32,
    __half* __restrict__ C16, int ldc16,
    const float* __restrict__ bias)
{
    extern __shared__ char shb[];
    constexpr int MT   = BMt / 32;           // m-frags per warp (1 or 2)
    constexpr int STGB = (BMt + BN) * ROWB;  // bytes per stage

    const int n0  = blockIdx.x * BN;
    const int m0  = blockIdx.y * BMt;
    const int tid = threadIdx.x;
    const int warp = tid >> 5, lane = tid & 31;
    const int wm = (warp >> 2) * (16 * MT);
    const int wn = (warp & 3) * 32;
    const int g  = lane >> 2, t = lane & 3;

    float acc[MT][4][4];
    #pragma unroll
    for (int mt = 0; mt < MT; mt++)
        #pragma unroll
        for (int nt = 0; nt < 4; nt++)
            #pragma unroll
            for (int i = 0; i < 4; i++) acc[mt][nt][i] = 0.f;

    const __half* Ab = A + (size_t)m0 * KD;
    const __half* Bb = B + (size_t)n0 * KD;

    // Stage row = 128 B = 8 x 16B chunks; dest col swizzled by row.
    auto load_stage = [&](int s, int k0) {
        char* as = shb + (s % NSTG) * STGB;
        char* bs = as + BMt * ROWB;
        #pragma unroll
        for (int i = 0; i < BMt / 32; ++i) {     // A: BMt rows x 8 chunks
            int idx = tid + 256 * i;
            int r = idx >> 3, cb = (idx & 7) * 16;
            CP_ASYNC16(as + r * ROWB + SWZ(r, cb), Ab + (size_t)r * KD + k0 + (idx & 7) * 8);
        }
        #pragma unroll
        for (int i = 0; i < 4; ++i) {            // B: 128 rows x 8 chunks
            int idx = tid + 256 * i;
            int r = idx >> 3, cb = (idx & 7) * 16;
            CP_ASYNC16(bs + r * ROWB + SWZ(r, cb), Bb + (size_t)r * KD + k0 + (idx & 7) * 8);
        }
        asm volatile("cp.async.commit_group;\n" ::);
    };

    const int NKt = KD / BKH;   // 8
    load_stage(0, 0);
    load_stage(1, BKH);

    // ldmatrix lane->row/col (bytes)
    const int rowA  = lane & 15;
    const int selA  = ((lane >> 4) & 1) * 16;
    const int rowB  = lane & 7;
    const int nselB = ((lane >> 4) & 1) * 8;
    const int selB  = ((lane >> 3) & 1) * 16;

    auto ldsm_frags = [&](const char* as, const char* bs, int kb2,
                          uint32_t af[][4], uint32_t bf[][2]) {
        #pragma unroll
        for (int mt = 0; mt < MT; mt++) {
            int r = wm + mt * 16 + rowA;
            ldm_x4(af[mt][0], af[mt][1], af[mt][2], af[mt][3],
                   as + r * ROWB + SWZ(r, kb2 + selA));
        }
        #pragma unroll
        for (int p = 0; p < 2; p++) {
            int r = wn + p * 16 + nselB + rowB;
            ldm_x4(bf[2*p][0], bf[2*p][1], bf[2*p+1][0], bf[2*p+1][1],
                   bs + r * ROWB + SWZ(r, kb2 + selB));
        }
    };

    auto mma_block = [&](uint32_t af[][4], uint32_t bf[][2]) {
        #pragma unroll
        for (int mt = 0; mt < MT; mt++)
            #pragma unroll
            for (int nt = 0; nt < 4; nt++)
                mma_fp16(acc[mt][nt], af[mt], bf[nt]);
    };

    uint32_t af[2][MT][4], bf[2][4][2];          // double-buffered fragments

    for (int kt = 0; kt < NKt; ++kt) {
        if (kt + 1 < NKt) asm volatile("cp.async.wait_group 1;\n" ::);
        else              asm volatile("cp.async.wait_group 0;\n" ::);
        __syncthreads();                         // single barrier per iter

        const char* as = shb + (kt % NSTG) * STGB;
        const char* bs = as + BMt * ROWB;

        ldsm_frags(as, bs, 0, af[0], bf[0]);     // chunk 0 into buf 0
        if (kt + 2 < NKt) load_stage(kt + 2, (kt + 2) * BKH);

        #pragma unroll
        for (int ch = 0; ch < 4; ++ch) {         // chunks 32 B apart
            if (ch < 3)
                ldsm_frags(as, bs, (ch + 1) * 32, af[(ch + 1) & 1], bf[(ch + 1) & 1]);
            mma_block(af[ch & 1], bf[ch & 1]);
        }
    }

    const bool f32out = (n0 < NSPLIT);
    #pragma unroll
    for (int mt = 0; mt < MT; mt++) {
        int r = m0 + wm + mt * 16 + g;
        #pragma unroll
        for (int nt = 0; nt < 4; nt++) {
            int c = n0 + wn + nt * 8 + 2 * t;
            float o0 = acc[mt][nt][0], o1 = acc[mt][nt][1];
            float o2 = acc[mt][nt][2], o3 = acc[mt][nt][3];
            if (HAS_BIAS) {
                float b0 = bias[c], b1 = bias[c + 1];
                o0 += b0; o1 += b1; o2 += b0; o3 += b1;
            }
            if (f32out) {
                *(float2*)&C32[(size_t)(r    ) * ldc32 + c] = make_float2(o0, o1);
                *(float2*)&C32[(size_t)(r + 8) * ldc32 + c] = make_float2(o2, o3);
            } else {
                int c16 = c - NSPLIT;
                *(__half2*)&C16[(size_t)(r    ) * ldc16 + c16] = __floats2half2_rn(o0, o1);
                *(__half2*)&C16[(size_t)(r + 8) * ldc16 + c16] = __floats2half2_rn(o2, o3);
            }
        }
    }
}

// ---------------------------------------------------------------------------
// K2: attention (round-12 winner). Warp = (row, head-pair), 16 lanes/head,
// float4 gathers, 5 pipelined width-16 reductions, softmax, V mix.
// ---------------------------------------------------------------------------
__global__ __launch_bounds__(256) void attn_kernel(const float* __restrict__ qb,
                                                   const float* __restrict__ kb,
                                                   const float* __restrict__ vb) {
    int w    = (blockIdx.x * blockDim.x + threadIdx.x) >> 5;
    int lane = threadIdx.x & 31;
    if (w >= MTOT * (HH / 2)) return;

    int hp  = w & 3;
    int row = w >> 2;
    int l   = row & (LL - 1);
    int b   = row >> 11;
    int h   = hp * 2 + (lane >> 4);
    int li  = lane & 15;
    int d   = 1 << (h & 3);

    const float4* QK4 = (const float4*)g_PQK;
    const int NQK4 = NQK / 4;
    int qoff = h * HW;
    int e0   = li * 4;

    float4 q = QK4[(size_t)row * NQK4 + ((qoff + e0) >> 2)];
    {
        float4 qb4 = ((const float4*)qb)[(qoff + e0) >> 2];
        q.x += qb4.x; q.y += qb4.y; q.z += qb4.z; q.w += qb4.w;
    }

    float  p[KT];
    float4 vv[KT];
    #pragma unroll
    for (int kk = 0; kk < KT; ++kk) {
        int sl   = l + (kk - 2) * d;
        int kidx = (h * KT + kk) * HW + e0;
        float4 kb4 = ((const float4*)kb)[kidx >> 2];
        float4 vb4 = ((const float4*)vb)[kidx >> 2];
        float4 kf, vf;
        if (sl >= 0 && sl < LL) {
            int srow = b * LL + sl;
            kf = QK4[(size_t)srow * NQK4 + ((KBASE + kidx) >> 2)];
            uint2 vraw = *(const uint2*)(g_PV + (size_t)srow * NKV_ + kidx);
            __half2 v01 = *(__half2*)&vraw.x, v23 = *(__half2*)&vraw.y;
            float2 f01 = __half22float2(v01), f23 = __half22float2(v23);
            kf.x += kb4.x; kf.y += kb4.y; kf.z += kb4.z; kf.w += kb4.w;
            vf = make_float4(f01.x + vb4.x, f01.y + vb4.y,
                             f23.x + vb4.z, f23.y + vb4.w);
        } else {
            kf = kb4;
            vf = vb4;
        }
        vv[kk] = vf;
        p[kk] = q.x * kf.x + q.y * kf.y + q.z * kf.z + q.w * kf.w;
    }

    #pragma unroll
    for (int s = 8; s > 0; s >>= 1)
        #pragma unroll
        for (int kk = 0; kk < KT; ++kk)
            p[kk] += __shfl_xor_sync(0xffffffffu, p[kk], s);

    float mx = p[0];
    #pragma unroll
    for (int kk = 1; kk < KT; ++kk) mx = fmaxf(mx, p[kk]);
    float e[KT], se = 0.f;
    #pragma unroll
    for (int kk = 0; kk < KT; ++kk) { e[kk] = __expf(p[kk] - mx); se += e[kk]; }
    float inv = 0.125f / se;

    float4 a = make_float4(0.f, 0.f, 0.f, 0.f);
    #pragma unroll
    for (int kk = 0; kk < KT; ++kk) {
        a.x += e[kk] * vv[kk].x; a.y += e[kk] * vv[kk].y;
        a.z += e[kk] * vv[kk].z; a.w += e[kk] * vv[kk].w;
    }
    a.x *= inv; a.y *= inv; a.z *= inv; a.w *= inv;

    __half2 o01 = __floats2half2_rn(a.x, a.y);
    __half2 o23 = __floats2half2_rn(a.z, a.w);
    uint2 out; out.x = *(uint32_t*)&o01; out.y = *(uint32_t*)&o23;
    *(uint2*)(g_ATTN + (size_t)row * DM + qoff + e0) = out;
}

// ---------------------------------------------------------------------------
// Launch
// ---------------------------------------------------------------------------
extern "C" void kernel_launch(void* const* d_in, const int* in_sizes, int n_in,
                              void* d_out, int out_size) {
    const float* x   = (const float*)d_in[0];
    const float* q_w = (const float*)d_in[1];
    const float* q_b = (const float*)d_in[2];
    const float* k_w = (const float*)d_in[3];
    const float* k_b = (const float*)d_in[4];
    const float* v_w = (const float*)d_in[5];
    const float* v_b = (const float*)d_in[6];
    const float* o_w = (const float*)d_in[7];
    const float* o_b = (const float*)d_in[8];

    __half *Xh, *Wh, *OWh, *PV, *ATTN;
    float *PQK;
    cudaGetSymbolAddress((void**)&Xh,   g_Xh);
    cudaGetSymbolAddress((void**)&Wh,   g_Wh);
    cudaGetSymbolAddress((void**)&OWh,  g_OWh);
    cudaGetSymbolAddress((void**)&PQK,  g_PQK);
    cudaGetSymbolAddress((void**)&PV,   g_PV);
    cudaGetSymbolAddress((void**)&ATTN, g_ATTN);

    const int smem1 = NSTG * (64 + BN) * ROWB;       // 73728 B
    const int smem3 = NSTG * (32 + BN) * ROWB;       // 61440 B
    cudaFuncSetAttribute(gemm_fp16<64, NQK, false>,
                         cudaFuncAttributeMaxDynamicSharedMemorySize, smem1);
    cudaFuncSetAttribute(gemm_fp16<32, DM, true>,
                         cudaFuncAttributeMaxDynamicSharedMemorySize, smem3);

    // K0: convert to fp16 (vectorized)
    prep_kernel<<<(PREP4 + 255) / 256, 256>>>(x, q_w, k_w, v_w, o_w);

    // K1: cols 0..3071 -> PQK fp32, cols 3072..5631 -> PV fp16
    gemm_fp16<64, NQK, false><<<dim3(NTOT / BN, MTOT / 64), 256, smem1>>>(
        Xh, Wh, PQK, NQK, PV, NKV_, nullptr);

    // K2: attention -> ATTN[4096, 512] fp16
    attn_kernel<<<(MTOT * (HH / 2) * 32) / 256, 256>>>(q_b, k_b, v_b);

    // K3: OUT = ATTN @ OWh^T + o_b  (BMt=32 -> 512 CTAs, full SM fill)
    gemm_fp16<32, DM, true><<<dim3(DM / BN, MTOT / 32), 256, smem3>>>(
        ATTN, OWh, (float*)d_out, DM, (__half*)nullptr, 0, o_b);
}

// round 17
// speedup vs baseline: 1.4479x; 1.0385x over previous
#include <cuda_runtime.h>
#include <cuda_fp16.h>
#include <cstdint>

// ---------------------------------------------------------------------------
// Problem constants
// ---------------------------------------------------------------------------
#define BB   2
#define LL   2048
#define DM   512
#define HH   8
#define KT   5
#define HW   64
#define MTOT (BB*LL)                  // 4096
#define NKV_ (HH*KT*HW)               // 2560
#define NQK  (DM + NKV_)              // 3072  (q then k)
#define NTOT (NQK + NKV_)             // 5632
#define KBASE (DM)                    // k starts at col 512 in PQK
#define KD   512

// ---------------------------------------------------------------------------
// Device scratch
// ---------------------------------------------------------------------------
__device__ __half g_Xh  [(size_t)MTOT * KD];      //  4.2 MB
__device__ __half g_Wh  [(size_t)NTOT * KD];      //  5.8 MB [qw;kw;vw]
__device__ __half g_OWh [(size_t)DM * KD];        //  0.5 MB
__device__ float  g_PQK [(size_t)MTOT * NQK];     // 50.3 MB fp32 q,k projections
__device__ __half g_PV  [(size_t)MTOT * NKV_];    // 21.0 MB fp16 v projections
__device__ __half g_ATTN[(size_t)MTOT * DM];      //  4.2 MB

// ---------------------------------------------------------------------------
// Helpers
// ---------------------------------------------------------------------------
__device__ __forceinline__ void ldm_x4(uint32_t& r0, uint32_t& r1, uint32_t& r2, uint32_t& r3,
                                       const void* p) {
    uint32_t a = (uint32_t)__cvta_generic_to_shared(p);
    asm volatile("ldmatrix.sync.aligned.m8n8.x4.shared.b16 {%0,%1,%2,%3}, [%4];"
                 : "=r"(r0), "=r"(r1), "=r"(r2), "=r"(r3) : "r"(a));
}

__device__ __forceinline__ void mma_fp16(float d[4], const uint32_t a[4], const uint32_t b[2]) {
    asm volatile(
        "mma.sync.aligned.m16n8k16.row.col.f32.f16.f16.f32 "
        "{%0,%1,%2,%3}, {%4,%5,%6,%7}, {%8,%9}, {%0,%1,%2,%3};\n"
        : "+f"(d[0]), "+f"(d[1]), "+f"(d[2]), "+f"(d[3])
        : "r"(a[0]), "r"(a[1]), "r"(a[2]), "r"(a[3]), "r"(b[0]), "r"(b[1]));
}

#define CP_ASYNC16(smem_ptr, gptr) \
    asm volatile("cp.async.cg.shared.global [%0], [%1], 16;\n" \
                 :: "r"((uint32_t)__cvta_generic_to_shared(smem_ptr)), "l"(gptr))

// ---------------------------------------------------------------------------
// K0: convert inputs to fp16, float4-vectorized
// ---------------------------------------------------------------------------
#define NX_  (MTOT*KD)
#define NQW_ (DM*KD)
#define NKW_ (NKV_*KD)
#define NW_  (NQW_ + 2*NKW_)
#define NX4  (NX_/4)
#define NQW4 (NQW_/4)
#define NKW4 (NKW_/4)
#define NW4  (NW_/4)
#define PREP4 (NX4 + NW4 + NQW4)

__device__ __forceinline__ void cvt4(__half* dst, float4 f) {
    __half2* d2 = (__half2*)dst;
    d2[0] = __floats2half2_rn(f.x, f.y);
    d2[1] = __floats2half2_rn(f.z, f.w);
}

__global__ void prep_kernel(const float* __restrict__ x,
                            const float* __restrict__ qw,
                            const float* __restrict__ kw,
                            const float* __restrict__ vw,
                            const float* __restrict__ ow) {
    int i = blockIdx.x * blockDim.x + threadIdx.x;
    if (i >= PREP4) return;
    if (i < NX4) {
        cvt4(g_Xh + 4 * (size_t)i, ((const float4*)x)[i]);
    } else {
        int j = i - NX4;
        if (j < NW4) {
            float4 f;
            if (j < NQW4)            f = ((const float4*)qw)[j];
            else if (j < NQW4+NKW4)  f = ((const float4*)kw)[j - NQW4];
            else                     f = ((const float4*)vw)[j - NQW4 - NKW4];
            cvt4(g_Wh + 4 * (size_t)j, f);
        } else {
            int p = j - NW4;
            cvt4(g_OWh + 4 * (size_t)p, ((const float4*)ow)[p]);
        }
    }
}

// ---------------------------------------------------------------------------
// Shared GEMM constants
// ---------------------------------------------------------------------------
#define BN  128
#define BKH 64
#define NSTG 3
#define ROWB 128                       // bytes per smem row (64 fp16)
#define SWZ(r, cb) ((cb) ^ (((r) & 7) << 4))

// ---------------------------------------------------------------------------
// K1: fp16 GEMM, 128 threads (4 warps, 2x2), CTA 64x128, warp tile 32x64.
// 16 MMAs per 6 LDSM per chunk (ratio 2.67). SW128 swizzle, BK=64, 3-stage
// cp.async, single barrier per K-iter, fragment double-buffering.
// 3 CTAs/SM (73.7 KB smem each) = 12 warps/SM.
// Mixed output: n0 < NQK -> fp32 PQK, else fp16 PV.
// ---------------------------------------------------------------------------
#define BM1 64
#define STGB1 ((BM1 + BN) * ROWB)      // 24576 B

__global__ __launch_bounds__(128, 3) void gemm_k1(
    const __half* __restrict__ A, const __half* __restrict__ B,
    float* __restrict__ C32, __half* __restrict__ C16)
{
    extern __shared__ char shb[];

    const int n0  = blockIdx.x * BN;
    const int m0  = blockIdx.y * BM1;
    const int tid = threadIdx.x;
    const int warp = tid >> 5, lane = tid & 31;
    const int wm = (warp >> 1) * 32;     // 0, 32
    const int wn = (warp & 1) * 64;      // 0, 64
    const int g  = lane >> 2, t = lane & 3;

    float acc[2][8][4];
    #pragma unroll
    for (int mt = 0; mt < 2; mt++)
        #pragma unroll
        for (int nt = 0; nt < 8; nt++)
            #pragma unroll
            for (int i = 0; i < 4; i++) acc[mt][nt][i] = 0.f;

    const __half* Ab = A + (size_t)m0 * KD;
    const __half* Bb = B + (size_t)n0 * KD;

    auto load_stage = [&](int s, int k0) {
        char* as = shb + (s % NSTG) * STGB1;
        char* bs = as + BM1 * ROWB;
        #pragma unroll
        for (int i = 0; i < 4; ++i) {            // A: 512 chunks (64 rows)
            int idx = tid + 128 * i;
            int r = idx >> 3, cb = (idx & 7) * 16;
            CP_ASYNC16(as + r * ROWB + SWZ(r, cb), Ab + (size_t)r * KD + k0 + (idx & 7) * 8);
        }
        #pragma unroll
        for (int i = 0; i < 8; ++i) {            // B: 1024 chunks (128 rows)
            int idx = tid + 128 * i;
            int r = idx >> 3, cb = (idx & 7) * 16;
            CP_ASYNC16(bs + r * ROWB + SWZ(r, cb), Bb + (size_t)r * KD + k0 + (idx & 7) * 8);
        }
        asm volatile("cp.async.commit_group;\n" ::);
    };

    const int NKt = KD / BKH;   // 8
    load_stage(0, 0);
    load_stage(1, BKH);

    const int rowA  = lane & 15;
    const int selA  = ((lane >> 4) & 1) * 16;
    const int rowB  = lane & 7;
    const int nselB = ((lane >> 4) & 1) * 8;
    const int selB  = ((lane >> 3) & 1) * 16;

    auto ldsm_frags = [&](const char* as, const char* bs, int kb2,
                          uint32_t af[][4], uint32_t bf[][2]) {
        #pragma unroll
        for (int mt = 0; mt < 2; mt++) {
            int r = wm + mt * 16 + rowA;
            ldm_x4(af[mt][0], af[mt][1], af[mt][2], af[mt][3],
                   as + r * ROWB + SWZ(r, kb2 + selA));
        }
        #pragma unroll
        for (int p = 0; p < 4; p++) {
            int r = wn + p * 16 + nselB + rowB;
            ldm_x4(bf[2*p][0], bf[2*p][1], bf[2*p+1][0], bf[2*p+1][1],
                   bs + r * ROWB + SWZ(r, kb2 + selB));
        }
    };

    auto mma_block = [&](uint32_t af[][4], uint32_t bf[][2]) {
        #pragma unroll
        for (int mt = 0; mt < 2; mt++)
            #pragma unroll
            for (int nt = 0; nt < 8; nt++)
                mma_fp16(acc[mt][nt], af[mt], bf[nt]);
    };

    uint32_t af[2][2][4], bf[2][8][2];           // double-buffered fragments

    for (int kt = 0; kt < NKt; ++kt) {
        if (kt + 1 < NKt) asm volatile("cp.async.wait_group 1;\n" ::);
        else              asm volatile("cp.async.wait_group 0;\n" ::);
        __syncthreads();                         // single barrier per iter

        const char* as = shb + (kt % NSTG) * STGB1;
        const char* bs = as + BM1 * ROWB;

        ldsm_frags(as, bs, 0, af[0], bf[0]);
        if (kt + 2 < NKt) load_stage(kt + 2, (kt + 2) * BKH);

        #pragma unroll
        for (int ch = 0; ch < 4; ++ch) {
            if (ch < 3)
                ldsm_frags(as, bs, (ch + 1) * 32, af[(ch + 1) & 1], bf[(ch + 1) & 1]);
            mma_block(af[ch & 1], bf[ch & 1]);
        }
    }

    const bool f32out = (n0 < NQK);
    #pragma unroll
    for (int mt = 0; mt < 2; mt++) {
        int r = m0 + wm + mt * 16 + g;
        #pragma unroll
        for (int nt = 0; nt < 8; nt++) {
            int c = n0 + wn + nt * 8 + 2 * t;
            if (f32out) {
                *(float2*)&C32[(size_t)(r    ) * NQK + c] =
                    make_float2(acc[mt][nt][0], acc[mt][nt][1]);
                *(float2*)&C32[(size_t)(r + 8) * NQK + c] =
                    make_float2(acc[mt][nt][2], acc[mt][nt][3]);
            } else {
                int c16 = c - NQK;
                *(__half2*)&C16[(size_t)(r    ) * NKV_ + c16] =
                    __floats2half2_rn(acc[mt][nt][0], acc[mt][nt][1]);
                *(__half2*)&C16[(size_t)(r + 8) * NKV_ + c16] =
                    __floats2half2_rn(acc[mt][nt][2], acc[mt][nt][3]);
            }
        }
    }
}

// ---------------------------------------------------------------------------
// K3: fp16 GEMM, 256 threads, CTA 64x128, warp tile 32x32 (round-15 winner).
// SW128 swizzle, BK=64, 3-stage, single barrier, frag double-buffering.
// fp32 out + bias.
// ---------------------------------------------------------------------------
#define BM3 64
#define STGB3 ((BM3 + BN) * ROWB)

__global__ __launch_bounds__(256, 2) void gemm_k3(
    const __half* __restrict__ A, const __half* __restrict__ B,
    float* __restrict__ C, int ldc, const float* __restrict__ bias)
{
    extern __shared__ char shb[];

    const int n0  = blockIdx.x * BN;
    const int m0  = blockIdx.y * BM3;
    const int tid = threadIdx.x;
    const int warp = tid >> 5, lane = tid & 31;
    const int wm = (warp >> 2) * 32;
    const int wn = (warp & 3) * 32;
    const int g  = lane >> 2, t = lane & 3;

    float acc[2][4][4];
    #pragma unroll
    for (int mt = 0; mt < 2; mt++)
        #pragma unroll
        for (int nt = 0; nt < 4; nt++)
            #pragma unroll
            for (int i = 0; i < 4; i++) acc[mt][nt][i] = 0.f;

    const __half* Ab = A + (size_t)m0 * KD;
    const __half* Bb = B + (size_t)n0 * KD;

    auto load_stage = [&](int s, int k0) {
        char* as = shb + (s % NSTG) * STGB3;
        char* bs = as + BM3 * ROWB;
        #pragma unroll
        for (int i = 0; i < 2; ++i) {
            int idx = tid + 256 * i;
            int r = idx >> 3, cb = (idx & 7) * 16;
            CP_ASYNC16(as + r * ROWB + SWZ(r, cb), Ab + (size_t)r * KD + k0 + (idx & 7) * 8);
        }
        #pragma unroll
        for (int i = 0; i < 4; ++i) {
            int idx = tid + 256 * i;
            int r = idx >> 3, cb = (idx & 7) * 16;
            CP_ASYNC16(bs + r * ROWB + SWZ(r, cb), Bb + (size_t)r * KD + k0 + (idx & 7) * 8);
        }
        asm volatile("cp.async.commit_group;\n" ::);
    };

    const int NKt = KD / BKH;
    load_stage(0, 0);
    load_stage(1, BKH);

    const int rowA  = lane & 15;
    const int selA  = ((lane >> 4) & 1) * 16;
    const int rowB  = lane & 7;
    const int nselB = ((lane >> 4) & 1) * 8;
    const int selB  = ((lane >> 3) & 1) * 16;

    auto ldsm_frags = [&](const char* as, const char* bs, int kb2,
                          uint32_t af[][4], uint32_t bf[][2]) {
        #pragma unroll
        for (int mt = 0; mt < 2; mt++) {
            int r = wm + mt * 16 + rowA;
            ldm_x4(af[mt][0], af[mt][1], af[mt][2], af[mt][3],
                   as + r * ROWB + SWZ(r, kb2 + selA));
        }
        #pragma unroll
        for (int p = 0; p < 2; p++) {
            int r = wn + p * 16 + nselB + rowB;
            ldm_x4(bf[2*p][0], bf[2*p][1], bf[2*p+1][0], bf[2*p+1][1],
                   bs + r * ROWB + SWZ(r, kb2 + selB));
        }
    };

    auto mma_block = [&](uint32_t af[][4], uint32_t bf[][2]) {
        #pragma unroll
        for (int mt = 0; mt < 2; mt++)
            #pragma unroll
            for (int nt = 0; nt < 4; nt++)
                mma_fp16(acc[mt][nt], af[mt], bf[nt]);
    };

    uint32_t af[2][2][4], bf[2][4][2];

    for (int kt = 0; kt < NKt; ++kt) {
        if (kt + 1 < NKt) asm volatile("cp.async.wait_group 1;\n" ::);
        else              asm volatile("cp.async.wait_group 0;\n" ::);
        __syncthreads();

        const char* as = shb + (kt % NSTG) * STGB3;
        const char* bs = as + BM3 * ROWB;

        ldsm_frags(as, bs, 0, af[0], bf[0]);
        if (kt + 2 < NKt) load_stage(kt + 2, (kt + 2) * BKH);

        #pragma unroll
        for (int ch = 0; ch < 4; ++ch) {
            if (ch < 3)
                ldsm_frags(as, bs, (ch + 1) * 32, af[(ch + 1) & 1], bf[(ch + 1) & 1]);
            mma_block(af[ch & 1], bf[ch & 1]);
        }
    }

    #pragma unroll
    for (int mt = 0; mt < 2; mt++) {
        int r = m0 + wm + mt * 16 + g;
        #pragma unroll
        for (int nt = 0; nt < 4; nt++) {
            int c = n0 + wn + nt * 8 + 2 * t;
            float b0 = bias[c], b1 = bias[c + 1];
            *(float2*)&C[(size_t)(r    ) * ldc + c] =
                make_float2(acc[mt][nt][0] + b0, acc[mt][nt][1] + b1);
            *(float2*)&C[(size_t)(r + 8) * ldc + c] =
                make_float2(acc[mt][nt][2] + b0, acc[mt][nt][3] + b1);
        }
    }
}

// ---------------------------------------------------------------------------
// K2: attention (round-12 winner). Warp = (row, head-pair), 16 lanes/head,
// float4 gathers, 5 pipelined width-16 reductions, softmax, V mix.
// ---------------------------------------------------------------------------
__global__ __launch_bounds__(256) void attn_kernel(const float* __restrict__ qb,
                                                   const float* __restrict__ kb,
                                                   const float* __restrict__ vb) {
    int w    = (blockIdx.x * blockDim.x + threadIdx.x) >> 5;
    int lane = threadIdx.x & 31;
    if (w >= MTOT * (HH / 2)) return;

    int hp  = w & 3;
    int row = w >> 2;
    int l   = row & (LL - 1);
    int b   = row >> 11;
    int h   = hp * 2 + (lane >> 4);
    int li  = lane & 15;
    int d   = 1 << (h & 3);

    const float4* QK4 = (const float4*)g_PQK;
    const int NQK4 = NQK / 4;
    int qoff = h * HW;
    int e0   = li * 4;

    float4 q = QK4[(size_t)row * NQK4 + ((qoff + e0) >> 2)];
    {
        float4 qb4 = ((const float4*)qb)[(qoff + e0) >> 2];
        q.x += qb4.x; q.y += qb4.y; q.z += qb4.z; q.w += qb4.w;
    }

    float  p[KT];
    float4 vv[KT];
    #pragma unroll
    for (int kk = 0; kk < KT; ++kk) {
        int sl   = l + (kk - 2) * d;
        int kidx = (h * KT + kk) * HW + e0;
        float4 kb4 = ((const float4*)kb)[kidx >> 2];
        float4 vb4 = ((const float4*)vb)[kidx >> 2];
        float4 kf, vf;
        if (sl >= 0 && sl < LL) {
            int srow = b * LL + sl;
            kf = QK4[(size_t)srow * NQK4 + ((KBASE + kidx) >> 2)];
            uint2 vraw = *(const uint2*)(g_PV + (size_t)srow * NKV_ + kidx);
            __half2 v01 = *(__half2*)&vraw.x, v23 = *(__half2*)&vraw.y;
            float2 f01 = __half22float2(v01), f23 = __half22float2(v23);
            kf.x += kb4.x; kf.y += kb4.y; kf.z += kb4.z; kf.w += kb4.w;
            vf = make_float4(f01.x + vb4.x, f01.y + vb4.y,
                             f23.x + vb4.z, f23.y + vb4.w);
        } else {
            kf = kb4;
            vf = vb4;
        }
        vv[kk] = vf;
        p[kk] = q.x * kf.x + q.y * kf.y + q.z * kf.z + q.w * kf.w;
    }

    #pragma unroll
    for (int s = 8; s > 0; s >>= 1)
        #pragma unroll
        for (int kk = 0; kk < KT; ++kk)
            p[kk] += __shfl_xor_sync(0xffffffffu, p[kk], s);

    float mx = p[0];
    #pragma unroll
    for (int kk = 1; kk < KT; ++kk) mx = fmaxf(mx, p[kk]);
    float e[KT], se = 0.f;
    #pragma unroll
    for (int kk = 0; kk < KT; ++kk) { e[kk] = __expf(p[kk] - mx); se += e[kk]; }
    float inv = 0.125f / se;

    float4 a = make_float4(0.f, 0.f, 0.f, 0.f);
    #pragma unroll
    for (int kk = 0; kk < KT; ++kk) {
        a.x += e[kk] * vv[kk].x; a.y += e[kk] * vv[kk].y;
        a.z += e[kk] * vv[kk].z; a.w += e[kk] * vv[kk].w;
    }
    a.x *= inv; a.y *= inv; a.z *= inv; a.w *= inv;

    __half2 o01 = __floats2half2_rn(a.x, a.y);
    __half2 o23 = __floats2half2_rn(a.z, a.w);
    uint2 out; out.x = *(uint32_t*)&o01; out.y = *(uint32_t*)&o23;
    *(uint2*)(g_ATTN + (size_t)row * DM + qoff + e0) = out;
}

// ---------------------------------------------------------------------------
// Launch
// ---------------------------------------------------------------------------
extern "C" void kernel_launch(void* const* d_in, const int* in_sizes, int n_in,
                              void* d_out, int out_size) {
    const float* x   = (const float*)d_in[0];
    const float* q_w = (const float*)d_in[1];
    const float* q_b = (const float*)d_in[2];
    const float* k_w = (const float*)d_in[3];
    const float* k_b = (const float*)d_in[4];
    const float* v_w = (const float*)d_in[5];
    const float* v_b = (const float*)d_in[6];
    const float* o_w = (const float*)d_in[7];
    const float* o_b = (const float*)d_in[8];

    __half *Xh, *Wh, *OWh, *PV, *ATTN;
    float *PQK;
    cudaGetSymbolAddress((void**)&Xh,   g_Xh);
    cudaGetSymbolAddress((void**)&Wh,   g_Wh);
    cudaGetSymbolAddress((void**)&OWh,  g_OWh);
    cudaGetSymbolAddress((void**)&PQK,  g_PQK);
    cudaGetSymbolAddress((void**)&PV,   g_PV);
    cudaGetSymbolAddress((void**)&ATTN, g_ATTN);

    const int smem1 = NSTG * STGB1;                  // 73728 B
    const int smem3 = NSTG * STGB3;                  // 73728 B
    cudaFuncSetAttribute(gemm_k1,
                         cudaFuncAttributeMaxDynamicSharedMemorySize, smem1);
    cudaFuncSetAttribute(gemm_k3,
                         cudaFuncAttributeMaxDynamicSharedMemorySize, smem3);

    // K0: convert to fp16 (vectorized)
    prep_kernel<<<(PREP4 + 255) / 256, 256>>>(x, q_w, k_w, v_w, o_w);

    // K1: cols 0..3071 -> PQK fp32, cols 3072..5631 -> PV fp16
    gemm_k1<<<dim3(NTOT / BN, MTOT / BM1), 128, smem1>>>(Xh, Wh, PQK, PV);

    // K2: attention -> ATTN[4096, 512] fp16
    attn_kernel<<<(MTOT * (HH / 2) * 32) / 256, 256>>>(q_b, k_b, v_b);

    // K3: OUT = ATTN @ OWh^T + o_b
    gemm_k3<<<dim3(DM / BN, MTOT / BM3), 256, smem3>>>(
        ATTN, OWh, (float*)d_out, DM, o_b);
}